// round 12
// baseline (speedup 1.0000x reference)
#include <cuda_runtime.h>
#include <cstdint>

#define NU 100000
#define NG 20000
#define NE 1000000
#define NS 500000
#define HH 256

// ----------------------------------------------------------------------------
// Static device scratch (no runtime allocation allowed)
// ----------------------------------------------------------------------------
__device__ float d_xg[NG * 128];          // concat(x_game, emb_game)
__device__ float d_u0[(size_t)NU * HH];
__device__ float d_u1[(size_t)NU * HH];
__device__ float d_g0[NG * HH];
__device__ float d_g1[NG * HH];
__device__ float d_msg_g[NG * HH];
__device__ float d_y[NG * HH];
__device__ float d_msg_u[(size_t)NU * HH];

__device__ int   d_rp_ug[NG + 1];
__device__ int   d_rp_gu[NU + 1];
__device__ int   d_cur_ug[NG + 1];
__device__ int   d_cur_gu[NU + 1];
__device__ int   d_es_ug[NE];
__device__ float d_ws_ug[NE];
__device__ int   d_es_gu[NE];
__device__ float d_ws_gu[NE];
__device__ int   d_bsum[256];             // per-1024-chunk sums (20 + 98 used)

// ----------------------------------------------------------------------------
// Setup kernels
// ----------------------------------------------------------------------------
__global__ void k_concat(const float* __restrict__ xg64, const float* __restrict__ emb) {
    int i = blockIdx.x * blockDim.x + threadIdx.x;   // over NG*64
    if (i < NG * 64) {
        int r = i >> 6, c = i & 63;
        d_xg[r * 128 + c]      = xg64[i];
        d_xg[r * 128 + 64 + c] = emb[i];
    }
}

__global__ void k_zero_counts() {
    int i = blockIdx.x * blockDim.x + threadIdx.x;
    if (i <= NG) d_cur_ug[i] = 0;
    if (i <= NU) d_cur_gu[i] = 0;
}

__global__ void k_hist(const int* __restrict__ dug, const int* __restrict__ dgu) {
    int e = blockIdx.x * blockDim.x + threadIdx.x;
    if (e < NE) {
        atomicAdd(&d_cur_ug[dug[e]], 1);
        atomicAdd(&d_cur_gu[dgu[e]], 1);
    }
}

// ---- 3-phase exclusive scan over the two count arrays -----------------------
// Phase A: per-1024-chunk sums. grid = (98, 2), block = 256.
__global__ void k_blocksum() {
    int which = blockIdx.y;
    int n = which ? NU : NG;
    const int* cnt = which ? d_cur_gu : d_cur_ug;
    int base = blockIdx.x * 1024;
    if (base >= n) return;
    int tid = threadIdx.x;
    int s = 0;
#pragma unroll
    for (int i = 0; i < 4; i++) {
        int idx = base + tid + i * 256;
        if (idx < n) s += cnt[idx];
    }
    __shared__ int ws[8];
    int lane = tid & 31, wid = tid >> 5;
#pragma unroll
    for (int o = 16; o; o >>= 1) s += __shfl_down_sync(0xffffffffu, s, o);
    if (lane == 0) ws[wid] = s;
    __syncthreads();
    if (tid == 0) {
        int t = 0;
#pragma unroll
        for (int i = 0; i < 8; i++) t += ws[i];
        d_bsum[which * 128 + blockIdx.x] = t;
    }
}

// Phase B: scan the (small) chunk-sum arrays; also writes rp[n] totals.
__global__ void k_scanbsum() {
    if (threadIdx.x == 0) {
        int run = 0;
        for (int i = 0; i < 20; i++) { int v = d_bsum[i]; d_bsum[i] = run; run += v; }
        d_rp_ug[NG] = run;
        run = 0;
        for (int i = 0; i < 98; i++) { int v = d_bsum[128 + i]; d_bsum[128 + i] = run; run += v; }
        d_rp_gu[NU] = run;
    }
}

// Phase C: per-chunk exclusive scan + chunk offset. grid = (98, 2), block = 256.
__global__ void k_scanwrite() {
    int which = blockIdx.y;
    int n = which ? NU : NG;
    const int* cnt = which ? d_cur_gu : d_cur_ug;
    int* rp = which ? d_rp_gu : d_rp_ug;
    int base = blockIdx.x * 1024;
    if (base >= n) return;
    int tid = threadIdx.x;

    int x[4];
#pragma unroll
    for (int i = 0; i < 4; i++) {
        int idx = base + tid * 4 + i;
        x[i] = (idx < n) ? cnt[idx] : 0;
    }
    int p[4];
    p[0] = 0; p[1] = x[0]; p[2] = p[1] + x[1]; p[3] = p[2] + x[2];
    int tsum = p[3] + x[3];

    __shared__ int ws[8];
    int lane = tid & 31, wid = tid >> 5;
    int v = tsum;
#pragma unroll
    for (int o = 1; o < 32; o <<= 1) {
        int t = __shfl_up_sync(0xffffffffu, v, o);
        if (lane >= o) v += t;
    }
    if (lane == 31) ws[wid] = v;
    __syncthreads();
    if (wid == 0) {
        int w = (lane < 8) ? ws[lane] : 0;
#pragma unroll
        for (int o = 1; o < 8; o <<= 1) {
            int t = __shfl_up_sync(0xffffffffu, w, o);
            if (lane >= o) w += t;
        }
        if (lane < 8) ws[lane] = w;
    }
    __syncthreads();
    int off = d_bsum[which * 128 + blockIdx.x] + (v - tsum) + (wid ? ws[wid - 1] : 0);
#pragma unroll
    for (int i = 0; i < 4; i++) {
        int idx = base + tid * 4 + i;
        if (idx < n) rp[idx] = off + p[i];
    }
}

__global__ void k_cursor() {
    int i = blockIdx.x * blockDim.x + threadIdx.x;
    if (i <= NG) d_cur_ug[i] = d_rp_ug[i];
    if (i <= NU) d_cur_gu[i] = d_rp_gu[i];
}

__global__ void k_scatter(const int* __restrict__ sug, const int* __restrict__ dug,
                          const float* __restrict__ wug,
                          const int* __restrict__ sgu, const int* __restrict__ dgu,
                          const float* __restrict__ wgu) {
    int e = blockIdx.x * blockDim.x + threadIdx.x;
    if (e < NE) {
        int p = atomicAdd(&d_cur_ug[dug[e]], 1);
        d_es_ug[p] = sug[e];
        d_ws_ug[p] = wug[e];
        int q = atomicAdd(&d_cur_gu[dgu[e]], 1);
        d_es_gu[q] = sgu[e];
        d_ws_gu[q] = wgu[e];
    }
}

// ----------------------------------------------------------------------------
// Segment sum by CSR rows: out[row,:] = sum_j w_j * X[src_j,:]
// Block = 128 threads, one row per block. D=256 uses float2 lanes.
// ----------------------------------------------------------------------------
__global__ void k_segsum256(const float* __restrict__ X,
                            const int* __restrict__ rp,
                            const int* __restrict__ es,
                            const float* __restrict__ wv,
                            float* __restrict__ out) {
    constexpr int T = 128;
    int row = blockIdx.x;
    int beg = rp[row], end = rp[row + 1];
    int tid = threadIdx.x;

    float2 acc = make_float2(0.f, 0.f);
    __shared__ int   ss[T];
    __shared__ float sw[T];

    for (int base = beg; base < end; base += T) {
        int cnt = min(T, end - base);
        if (tid < cnt) { ss[tid] = es[base + tid]; sw[tid] = wv[base + tid]; }
        __syncthreads();
#pragma unroll 4
        for (int j = 0; j < cnt; j++) {
            const float2* xr = (const float2*)(X + (size_t)ss[j] * 256);
            float wj = sw[j];
            float2 x = xr[tid];
            acc.x += wj * x.x;
            acc.y += wj * x.y;
        }
        __syncthreads();
    }
    ((float2*)(out + (size_t)row * 256))[tid] = acc;
}

__global__ void k_segsum128(const float* __restrict__ X,
                            const int* __restrict__ rp,
                            const int* __restrict__ es,
                            const float* __restrict__ wv,
                            float* __restrict__ out) {
    constexpr int T = 128;
    int row = blockIdx.x;
    int beg = rp[row], end = rp[row + 1];
    int tid = threadIdx.x;

    float acc = 0.f;
    __shared__ int   ss[T];
    __shared__ float sw[T];

    for (int base = beg; base < end; base += T) {
        int cnt = min(T, end - base);
        if (tid < cnt) { ss[tid] = es[base + tid]; sw[tid] = wv[base + tid]; }
        __syncthreads();
#pragma unroll 4
        for (int j = 0; j < cnt; j++) {
            acc += sw[j] * X[(size_t)ss[j] * 128 + tid];
        }
        __syncthreads();
    }
    out[(size_t)row * 128 + tid] = acc;
}

// ----------------------------------------------------------------------------
// Fused SGEMM: C[M,256] = relu?( A1@W1 + (A2@W2)? + pre? + bias? )
// 128x128x16 tile, double-buffered smem, 256 threads, 8x8 microtile.
// Inner loop uses explicit float4 shared loads (As row pitch 132 floats =
// 528 B, a 16 B multiple, so all fragment loads are LDS.128).
// ----------------------------------------------------------------------------
__global__ __launch_bounds__(256)
void k_gemm(const float* __restrict__ A1, const float* __restrict__ W1, int K1,
            const float* __restrict__ A2, const float* __restrict__ W2, int K2,
            const float* __restrict__ pre, const float* __restrict__ bias,
            float* __restrict__ C, int M, int relu) {
    constexpr int BM = 128, BN = 128, BK = 16;
    __shared__ float As[2][BK][BM + 4];
    __shared__ float Bs[2][BK][BN];

    int tid = threadIdx.x;
    int tx = tid & 15;        // 0..15  (cols)
    int ty = tid >> 4;        // 0..15  (rows)
    int brow = blockIdx.x * BM;
    int bcol = blockIdx.y * BN;

    float acc[8][8];
#pragma unroll
    for (int i = 0; i < 8; i++)
#pragma unroll
        for (int j = 0; j < 8; j++) acc[i][j] = 0.f;

    // A tile loader: 128x16 = 512 float4s; this thread loads rows ar, ar+64
    int ar  = tid >> 2;            // 0..63
    int ac4 = (tid & 3) * 4;       // 0,4,8,12
    int gr0 = brow + ar, gr1 = brow + ar + 64;
    bool av0 = (gr0 < M), av1 = (gr1 < M);
    int cr0 = av0 ? gr0 : (M - 1);
    int cr1 = av1 ? gr1 : (M - 1);
    // W tile loader: 16x128 = 512 float4s; rows wr, wr+8
    int wr  = tid >> 5;            // 0..7
    int wc4 = (tid & 31) * 4;      // 0..124

    const float4 f4z = make_float4(0.f, 0.f, 0.f, 0.f);

    for (int pass = 0; pass < 2; pass++) {
        const float* A = pass ? A2 : A1;
        const float* W = pass ? W2 : W1;
        int K = pass ? K2 : K1;
        if (A == nullptr) continue;
        const float* Ap0 = A + (size_t)cr0 * K;
        const float* Ap1 = A + (size_t)cr1 * K;

        // guard: previous pass's last compute must finish before reuse of buffers
        __syncthreads();

        // preload tile k0=0 into buffer 0
        {
            float4 a0 = av0 ? *(const float4*)(Ap0 + ac4) : f4z;
            float4 a1 = av1 ? *(const float4*)(Ap1 + ac4) : f4z;
            float4 w0 = *(const float4*)(W + (size_t)wr * 256 + bcol + wc4);
            float4 w1 = *(const float4*)(W + (size_t)(wr + 8) * 256 + bcol + wc4);
            As[0][ac4 + 0][ar] = a0.x; As[0][ac4 + 1][ar] = a0.y;
            As[0][ac4 + 2][ar] = a0.z; As[0][ac4 + 3][ar] = a0.w;
            As[0][ac4 + 0][ar + 64] = a1.x; As[0][ac4 + 1][ar + 64] = a1.y;
            As[0][ac4 + 2][ar + 64] = a1.z; As[0][ac4 + 3][ar + 64] = a1.w;
            *(float4*)&Bs[0][wr][wc4] = w0;
            *(float4*)&Bs[0][wr + 8][wc4] = w1;
        }
        __syncthreads();

        int buf = 0;
        for (int k0 = 0; k0 < K; k0 += BK) {
            bool more = (k0 + BK) < K;
            float4 na0, na1, nw0, nw1;
            if (more) {
                int kn = k0 + BK;
                na0 = av0 ? *(const float4*)(Ap0 + kn + ac4) : f4z;
                na1 = av1 ? *(const float4*)(Ap1 + kn + ac4) : f4z;
                nw0 = *(const float4*)(W + (size_t)(kn + wr) * 256 + bcol + wc4);
                nw1 = *(const float4*)(W + (size_t)(kn + wr + 8) * 256 + bcol + wc4);
            }
#pragma unroll
            for (int k = 0; k < BK; k++) {
                float4 a0 = *(const float4*)&As[buf][k][ty * 8];
                float4 a1 = *(const float4*)&As[buf][k][ty * 8 + 4];
                float4 b0 = *(const float4*)&Bs[buf][k][tx * 8];
                float4 b1 = *(const float4*)&Bs[buf][k][tx * 8 + 4];
                float ra[8] = {a0.x, a0.y, a0.z, a0.w, a1.x, a1.y, a1.z, a1.w};
                float rb[8] = {b0.x, b0.y, b0.z, b0.w, b1.x, b1.y, b1.z, b1.w};
#pragma unroll
                for (int i = 0; i < 8; i++)
#pragma unroll
                    for (int j = 0; j < 8; j++) acc[i][j] += ra[i] * rb[j];
            }
            if (more) {
                int nb = buf ^ 1;
                As[nb][ac4 + 0][ar] = na0.x; As[nb][ac4 + 1][ar] = na0.y;
                As[nb][ac4 + 2][ar] = na0.z; As[nb][ac4 + 3][ar] = na0.w;
                As[nb][ac4 + 0][ar + 64] = na1.x; As[nb][ac4 + 1][ar + 64] = na1.y;
                As[nb][ac4 + 2][ar + 64] = na1.z; As[nb][ac4 + 3][ar + 64] = na1.w;
                *(float4*)&Bs[nb][wr][wc4] = nw0;
                *(float4*)&Bs[nb][wr + 8][wc4] = nw1;
                __syncthreads();
            }
            buf ^= 1;
        }
    }

    // Epilogue
    float bb[8];
#pragma unroll
    for (int j = 0; j < 8; j++) bb[j] = bias ? bias[bcol + tx * 8 + j] : 0.f;

#pragma unroll
    for (int i = 0; i < 8; i++) {
        int r = brow + ty * 8 + i;
        if (r >= M) continue;
        size_t off = (size_t)r * 256 + bcol + tx * 8;
#pragma unroll
        for (int j = 0; j < 8; j++) {
            float v = acc[i][j] + bb[j];
            if (pre) v += pre[off + j];
            if (relu) v = fmaxf(v, 0.f);
            C[off + j] = v;
        }
    }
}

// ----------------------------------------------------------------------------
// Decoder: out[s] = dot(u[row[s]], g[col[s]]) over 256 dims. One warp per s.
// ----------------------------------------------------------------------------
__global__ void k_decode(const float* __restrict__ u, const float* __restrict__ g,
                         const int* __restrict__ rows, const int* __restrict__ cols,
                         float* __restrict__ out) {
    int w = (blockIdx.x * blockDim.x + threadIdx.x) >> 5;
    int lane = threadIdx.x & 31;
    if (w >= NS) return;
    const float4* ur = (const float4*)(u + (size_t)rows[w] * 256);
    const float4* gr = (const float4*)(g + (size_t)cols[w] * 256);
    float acc = 0.f;
#pragma unroll
    for (int i = 0; i < 2; i++) {
        float4 a = ur[lane + i * 32];
        float4 b = gr[lane + i * 32];
        acc += a.x * b.x + a.y * b.y + a.z * b.z + a.w * b.w;
    }
#pragma unroll
    for (int o = 16; o; o >>= 1) acc += __shfl_down_sync(0xffffffffu, acc, o);
    if (lane == 0) out[w] = acc;
}

// ----------------------------------------------------------------------------
// Host side
// ----------------------------------------------------------------------------
static void run_layer(const float* u_prev, int du, const float* g_prev, int dg,
                      const float* Wr_ug, const float* b_ug, const float* Wo_g,
                      const float* Wr_gu, const float* b_gu, const float* Wo_u,
                      float* g_out, float* u_out, int relu,
                      float* p_msg_g, float* p_y, float* p_msg_u,
                      int* p_rp_ug, int* p_es_ug, float* p_ws_ug,
                      int* p_rp_gu, int* p_es_gu, float* p_ws_gu) {
    // users -> games (direct form): msg_g[NG,du] = segsum_ug(u_prev)
    if (du == 128)
        k_segsum128<<<NG, 128>>>(u_prev, p_rp_ug, p_es_ug, p_ws_ug, p_msg_g);
    else
        k_segsum256<<<NG, 128>>>(u_prev, p_rp_ug, p_es_ug, p_ws_ug, p_msg_g);
    // g_out = relu?(msg_g@Wr_ug + g_prev@Wo_g + b_ug)
    k_gemm<<<dim3((NG + 127) / 128, 2), 256>>>(p_msg_g, Wr_ug, du,
                                               g_prev, Wo_g, dg,
                                               nullptr, b_ug, g_out, NG, relu);
    // games -> users (commuted form): y = g_prev@Wr_gu  [NG,256]
    k_gemm<<<dim3((NG + 127) / 128, 2), 256>>>(g_prev, Wr_gu, dg,
                                               nullptr, nullptr, 0,
                                               nullptr, nullptr, p_y, NG, 0);
    // msg_u[NU,256] = segsum_gu(y)
    k_segsum256<<<NU, 128>>>(p_y, p_rp_gu, p_es_gu, p_ws_gu, p_msg_u);
    // u_out = relu?(msg_u + u_prev@Wo_u + b_gu)
    k_gemm<<<dim3((NU + 127) / 128, 2), 256>>>(u_prev, Wo_u, du,
                                               nullptr, nullptr, 0,
                                               p_msg_u, b_gu, u_out, NU, relu);
}

extern "C" void kernel_launch(void* const* d_in, const int* in_sizes, int n_in,
                              void* d_out, int out_size) {
    // ---- input mapping (handles both metadata orderings) ----
    const float *x_user, *x_game, *emb_game, *ew_ug, *ew_gu;
    const int *src_ug, *dst_ug, *src_gu, *dst_gu, *srow, *scol;
    const float *Wrug[3], *bug[3], *Wog[3], *Wrgu[3], *bgu[3], *Wou[3];

    x_user   = (const float*)d_in[0];
    x_game   = (const float*)d_in[1];
    emb_game = (const float*)d_in[2];
    ew_ug    = (const float*)d_in[3];
    ew_gu    = (const float*)d_in[4];

    if (in_sizes[5] == NE) {
        // setup_inputs dict order
        src_ug = (const int*)d_in[5];
        dst_ug = (const int*)d_in[6];
        src_gu = (const int*)d_in[7];
        dst_gu = (const int*)d_in[8];
        srow   = (const int*)d_in[9];
        scol   = (const int*)d_in[10];
        for (int l = 0; l < 3; l++) {
            int b = 11 + 6 * l;
            Wrug[l] = (const float*)d_in[b + 0];
            bug[l]  = (const float*)d_in[b + 1];
            Wog[l]  = (const float*)d_in[b + 2];
            Wrgu[l] = (const float*)d_in[b + 3];
            bgu[l]  = (const float*)d_in[b + 4];
            Wou[l]  = (const float*)d_in[b + 5];
        }
    } else {
        // reference signature order
        for (int l = 0; l < 3; l++) {
            int b = 5 + 6 * l;
            Wrug[l] = (const float*)d_in[b + 0];
            bug[l]  = (const float*)d_in[b + 1];
            Wog[l]  = (const float*)d_in[b + 2];
            Wrgu[l] = (const float*)d_in[b + 3];
            bgu[l]  = (const float*)d_in[b + 4];
            Wou[l]  = (const float*)d_in[b + 5];
        }
        src_ug = (const int*)d_in[23];
        dst_ug = (const int*)d_in[24];
        src_gu = (const int*)d_in[25];
        dst_gu = (const int*)d_in[26];
        srow   = (const int*)d_in[27];
        scol   = (const int*)d_in[28];
    }

    // ---- scratch symbol addresses ----
    float *p_xg, *p_u0, *p_u1, *p_g0, *p_g1, *p_msg_g, *p_y, *p_msg_u;
    float *p_ws_ug, *p_ws_gu;
    int *p_rp_ug, *p_rp_gu, *p_es_ug, *p_es_gu;
    cudaGetSymbolAddress((void**)&p_xg, d_xg);
    cudaGetSymbolAddress((void**)&p_u0, d_u0);
    cudaGetSymbolAddress((void**)&p_u1, d_u1);
    cudaGetSymbolAddress((void**)&p_g0, d_g0);
    cudaGetSymbolAddress((void**)&p_g1, d_g1);
    cudaGetSymbolAddress((void**)&p_msg_g, d_msg_g);
    cudaGetSymbolAddress((void**)&p_y, d_y);
    cudaGetSymbolAddress((void**)&p_msg_u, d_msg_u);
    cudaGetSymbolAddress((void**)&p_rp_ug, d_rp_ug);
    cudaGetSymbolAddress((void**)&p_rp_gu, d_rp_gu);
    cudaGetSymbolAddress((void**)&p_es_ug, d_es_ug);
    cudaGetSymbolAddress((void**)&p_es_gu, d_es_gu);
    cudaGetSymbolAddress((void**)&p_ws_ug, d_ws_ug);
    cudaGetSymbolAddress((void**)&p_ws_gu, d_ws_gu);

    float* out = (float*)d_out;

    // ---- setup: concat game features, build CSR (both directions) ----
    k_concat<<<(NG * 64 + 255) / 256, 256>>>(x_game, emb_game);
    k_zero_counts<<<(NU + 256) / 256, 256>>>();
    k_hist<<<(NE + 255) / 256, 256>>>(dst_ug, dst_gu);
    k_blocksum<<<dim3(98, 2), 256>>>();
    k_scanbsum<<<1, 32>>>();
    k_scanwrite<<<dim3(98, 2), 256>>>();
    k_cursor<<<(NU + 256) / 256, 256>>>();
    k_scatter<<<(NE + 255) / 256, 256>>>(src_ug, dst_ug, ew_ug,
                                         src_gu, dst_gu, ew_gu);

    // ---- 3 GraphConv layers ----
    run_layer(x_user, 128, p_xg, 128,
              Wrug[0], bug[0], Wog[0], Wrgu[0], bgu[0], Wou[0],
              p_g0, p_u0, 1,
              p_msg_g, p_y, p_msg_u,
              p_rp_ug, p_es_ug, p_ws_ug, p_rp_gu, p_es_gu, p_ws_gu);
    run_layer(p_u0, 256, p_g0, 256,
              Wrug[1], bug[1], Wog[1], Wrgu[1], bgu[1], Wou[1],
              p_g1, p_u1, 1,
              p_msg_g, p_y, p_msg_u,
              p_rp_ug, p_es_ug, p_ws_ug, p_rp_gu, p_es_gu, p_ws_gu);
    run_layer(p_u1, 256, p_g1, 256,
              Wrug[2], bug[2], Wog[2], Wrgu[2], bgu[2], Wou[2],
              p_g0, p_u0, 0,
              p_msg_g, p_y, p_msg_u,
              p_rp_ug, p_es_ug, p_ws_ug, p_rp_gu, p_es_gu, p_ws_gu);

    // ---- decoder ----
    k_decode<<<(NS * 32 + 255) / 256, 256>>>(p_u0, p_g0, srow, scol, out);
    (void)n_in; (void)out_size;
}

// round 13
// speedup vs baseline: 1.1572x; 1.1572x over previous
#include <cuda_runtime.h>
#include <cstdint>

#define NU 100000
#define NG 20000
#define NE 1000000
#define NS 500000
#define HH 256

// ----------------------------------------------------------------------------
// Static device scratch (no runtime allocation allowed)
// ----------------------------------------------------------------------------
__device__ float d_xg[NG * 128];          // concat(x_game, emb_game)
__device__ float d_u0[(size_t)NU * HH];
__device__ float d_u1[(size_t)NU * HH];
__device__ float d_g0[NG * HH];
__device__ float d_g1[NG * HH];
__device__ float d_msg_g[NG * HH];
__device__ float d_y[NG * HH];
__device__ float d_msg_u[(size_t)NU * HH];

__device__ int   d_rp_ug[NG + 1];
__device__ int   d_rp_gu[NU + 1];
__device__ int   d_cur_ug[NG + 1];
__device__ int   d_cur_gu[NU + 1];
__device__ int   d_es_ug[NE];
__device__ float d_ws_ug[NE];
__device__ int   d_es_gu[NE];
__device__ float d_ws_gu[NE];
__device__ int   d_bsum[256];             // per-1024-chunk sums (20 + 98 used)

// ----------------------------------------------------------------------------
// Setup kernels
// ----------------------------------------------------------------------------
__global__ void k_concat(const float* __restrict__ xg64, const float* __restrict__ emb) {
    int i = blockIdx.x * blockDim.x + threadIdx.x;   // over NG*64
    if (i < NG * 64) {
        int r = i >> 6, c = i & 63;
        d_xg[r * 128 + c]      = xg64[i];
        d_xg[r * 128 + 64 + c] = emb[i];
    }
}

__global__ void k_zero_counts() {
    int i = blockIdx.x * blockDim.x + threadIdx.x;
    if (i <= NG) d_cur_ug[i] = 0;
    if (i <= NU) d_cur_gu[i] = 0;
}

__global__ void k_hist(const int* __restrict__ dug, const int* __restrict__ dgu) {
    int e = blockIdx.x * blockDim.x + threadIdx.x;
    if (e < NE) {
        atomicAdd(&d_cur_ug[dug[e]], 1);
        atomicAdd(&d_cur_gu[dgu[e]], 1);
    }
}

// ---- 3-phase exclusive scan over the two count arrays -----------------------
// Phase A: per-1024-chunk sums. grid = (98, 2), block = 256.
__global__ void k_blocksum() {
    int which = blockIdx.y;
    int n = which ? NU : NG;
    const int* cnt = which ? d_cur_gu : d_cur_ug;
    int base = blockIdx.x * 1024;
    if (base >= n) return;
    int tid = threadIdx.x;
    int s = 0;
#pragma unroll
    for (int i = 0; i < 4; i++) {
        int idx = base + tid + i * 256;
        if (idx < n) s += cnt[idx];
    }
    __shared__ int ws[8];
    int lane = tid & 31, wid = tid >> 5;
#pragma unroll
    for (int o = 16; o; o >>= 1) s += __shfl_down_sync(0xffffffffu, s, o);
    if (lane == 0) ws[wid] = s;
    __syncthreads();
    if (tid == 0) {
        int t = 0;
#pragma unroll
        for (int i = 0; i < 8; i++) t += ws[i];
        d_bsum[which * 128 + blockIdx.x] = t;
    }
}

// Phase B: scan the (small) chunk-sum arrays; also writes rp[n] totals.
__global__ void k_scanbsum() {
    if (threadIdx.x == 0) {
        int run = 0;
        for (int i = 0; i < 20; i++) { int v = d_bsum[i]; d_bsum[i] = run; run += v; }
        d_rp_ug[NG] = run;
        run = 0;
        for (int i = 0; i < 98; i++) { int v = d_bsum[128 + i]; d_bsum[128 + i] = run; run += v; }
        d_rp_gu[NU] = run;
    }
}

// Phase C: per-chunk exclusive scan + chunk offset. grid = (98, 2), block = 256.
__global__ void k_scanwrite() {
    int which = blockIdx.y;
    int n = which ? NU : NG;
    const int* cnt = which ? d_cur_gu : d_cur_ug;
    int* rp = which ? d_rp_gu : d_rp_ug;
    int base = blockIdx.x * 1024;
    if (base >= n) return;
    int tid = threadIdx.x;

    int x[4];
#pragma unroll
    for (int i = 0; i < 4; i++) {
        int idx = base + tid * 4 + i;
        x[i] = (idx < n) ? cnt[idx] : 0;
    }
    int p[4];
    p[0] = 0; p[1] = x[0]; p[2] = p[1] + x[1]; p[3] = p[2] + x[2];
    int tsum = p[3] + x[3];

    __shared__ int ws[8];
    int lane = tid & 31, wid = tid >> 5;
    int v = tsum;
#pragma unroll
    for (int o = 1; o < 32; o <<= 1) {
        int t = __shfl_up_sync(0xffffffffu, v, o);
        if (lane >= o) v += t;
    }
    if (lane == 31) ws[wid] = v;
    __syncthreads();
    if (wid == 0) {
        int w = (lane < 8) ? ws[lane] : 0;
#pragma unroll
        for (int o = 1; o < 8; o <<= 1) {
            int t = __shfl_up_sync(0xffffffffu, w, o);
            if (lane >= o) w += t;
        }
        if (lane < 8) ws[lane] = w;
    }
    __syncthreads();
    int off = d_bsum[which * 128 + blockIdx.x] + (v - tsum) + (wid ? ws[wid - 1] : 0);
#pragma unroll
    for (int i = 0; i < 4; i++) {
        int idx = base + tid * 4 + i;
        if (idx < n) rp[idx] = off + p[i];
    }
}

__global__ void k_cursor() {
    int i = blockIdx.x * blockDim.x + threadIdx.x;
    if (i <= NG) d_cur_ug[i] = d_rp_ug[i];
    if (i <= NU) d_cur_gu[i] = d_rp_gu[i];
}

__global__ void k_scatter(const int* __restrict__ sug, const int* __restrict__ dug,
                          const float* __restrict__ wug,
                          const int* __restrict__ sgu, const int* __restrict__ dgu,
                          const float* __restrict__ wgu) {
    int e = blockIdx.x * blockDim.x + threadIdx.x;
    if (e < NE) {
        int p = atomicAdd(&d_cur_ug[dug[e]], 1);
        d_es_ug[p] = sug[e];
        d_ws_ug[p] = wug[e];
        int q = atomicAdd(&d_cur_gu[dgu[e]], 1);
        d_es_gu[q] = sgu[e];
        d_ws_gu[q] = wgu[e];
    }
}

// ----------------------------------------------------------------------------
// Segment sum, warp-per-row: out[row,:] = sum_j w_j * X[src_j,:]
// 8 warps per block, one CSR row per warp. Edge (src, w) broadcast via shfl.
// No shared memory, no barriers. D=256: lane owns cols [4l,4l+4) and
// [128+4l, 128+4l+4). D=128: lane owns cols [4l, 4l+4).
// ----------------------------------------------------------------------------
__global__ void k_segsum256(const float* __restrict__ X,
                            const int* __restrict__ rp,
                            const int* __restrict__ es,
                            const float* __restrict__ wv,
                            float* __restrict__ out, int nrows) {
    int row = blockIdx.x * 8 + (threadIdx.x >> 5);
    if (row >= nrows) return;
    int lane = threadIdx.x & 31;
    int beg = rp[row], end = rp[row + 1];

    float4 acc0 = make_float4(0.f, 0.f, 0.f, 0.f);
    float4 acc1 = make_float4(0.f, 0.f, 0.f, 0.f);

    for (int base = beg; base < end; base += 32) {
        int idx = base + lane;
        int   sj = (idx < end) ? es[idx] : 0;
        float wj = (idx < end) ? wv[idx] : 0.f;
        int cnt = min(32, end - base);
        for (int j = 0; j < cnt; j++) {
            int   s = __shfl_sync(0xffffffffu, sj, j);
            float w = __shfl_sync(0xffffffffu, wj, j);
            const float4* xr = (const float4*)(X + (size_t)s * 256);
            float4 x0 = xr[lane];
            float4 x1 = xr[lane + 32];
            acc0.x += w * x0.x; acc0.y += w * x0.y;
            acc0.z += w * x0.z; acc0.w += w * x0.w;
            acc1.x += w * x1.x; acc1.y += w * x1.y;
            acc1.z += w * x1.z; acc1.w += w * x1.w;
        }
    }
    float4* orow = (float4*)(out + (size_t)row * 256);
    orow[lane]      = acc0;
    orow[lane + 32] = acc1;
}

__global__ void k_segsum128(const float* __restrict__ X,
                            const int* __restrict__ rp,
                            const int* __restrict__ es,
                            const float* __restrict__ wv,
                            float* __restrict__ out, int nrows) {
    int row = blockIdx.x * 8 + (threadIdx.x >> 5);
    if (row >= nrows) return;
    int lane = threadIdx.x & 31;
    int beg = rp[row], end = rp[row + 1];

    float4 acc = make_float4(0.f, 0.f, 0.f, 0.f);

    for (int base = beg; base < end; base += 32) {
        int idx = base + lane;
        int   sj = (idx < end) ? es[idx] : 0;
        float wj = (idx < end) ? wv[idx] : 0.f;
        int cnt = min(32, end - base);
        for (int j = 0; j < cnt; j++) {
            int   s = __shfl_sync(0xffffffffu, sj, j);
            float w = __shfl_sync(0xffffffffu, wj, j);
            float4 x = ((const float4*)(X + (size_t)s * 128))[lane];
            acc.x += w * x.x; acc.y += w * x.y;
            acc.z += w * x.z; acc.w += w * x.w;
        }
    }
    ((float4*)(out + (size_t)row * 128))[lane] = acc;
}

// ----------------------------------------------------------------------------
// Fused SGEMM: C[M,256] = relu?( A1@W1 + (A2@W2)? + pre? + bias? )
// 128x128x16 tile, double-buffered smem, 256 threads, 8x8 microtile.
// Microkernel uses indexed smem reads (R11 form — ptxas vectorizes these;
// explicit float4 + register arrays regressed 300us in R12).
// ----------------------------------------------------------------------------
__global__ __launch_bounds__(256)
void k_gemm(const float* __restrict__ A1, const float* __restrict__ W1, int K1,
            const float* __restrict__ A2, const float* __restrict__ W2, int K2,
            const float* __restrict__ pre, const float* __restrict__ bias,
            float* __restrict__ C, int M, int relu) {
    constexpr int BM = 128, BN = 128, BK = 16;
    __shared__ float As[2][BK][BM + 4];
    __shared__ float Bs[2][BK][BN];

    int tid = threadIdx.x;
    int tx = tid & 15;        // 0..15  (cols)
    int ty = tid >> 4;        // 0..15  (rows)
    int brow = blockIdx.x * BM;
    int bcol = blockIdx.y * BN;

    float acc[8][8];
#pragma unroll
    for (int i = 0; i < 8; i++)
#pragma unroll
        for (int j = 0; j < 8; j++) acc[i][j] = 0.f;

    // A tile loader: 128x16 = 512 float4s; this thread loads rows ar, ar+64
    int ar  = tid >> 2;            // 0..63
    int ac4 = (tid & 3) * 4;       // 0,4,8,12
    int gr0 = brow + ar, gr1 = brow + ar + 64;
    bool av0 = (gr0 < M), av1 = (gr1 < M);
    int cr0 = av0 ? gr0 : (M - 1);
    int cr1 = av1 ? gr1 : (M - 1);
    // W tile loader: 16x128 = 512 float4s; rows wr, wr+8
    int wr  = tid >> 5;            // 0..7
    int wc4 = (tid & 31) * 4;      // 0..124

    const float4 f4z = make_float4(0.f, 0.f, 0.f, 0.f);

    for (int pass = 0; pass < 2; pass++) {
        const float* A = pass ? A2 : A1;
        const float* W = pass ? W2 : W1;
        int K = pass ? K2 : K1;
        if (A == nullptr) continue;
        const float* Ap0 = A + (size_t)cr0 * K;
        const float* Ap1 = A + (size_t)cr1 * K;

        // guard: previous pass's last compute must finish before reuse of buffers
        __syncthreads();

        // preload tile k0=0 into buffer 0
        {
            float4 a0 = av0 ? *(const float4*)(Ap0 + ac4) : f4z;
            float4 a1 = av1 ? *(const float4*)(Ap1 + ac4) : f4z;
            float4 w0 = *(const float4*)(W + (size_t)wr * 256 + bcol + wc4);
            float4 w1 = *(const float4*)(W + (size_t)(wr + 8) * 256 + bcol + wc4);
            As[0][ac4 + 0][ar] = a0.x; As[0][ac4 + 1][ar] = a0.y;
            As[0][ac4 + 2][ar] = a0.z; As[0][ac4 + 3][ar] = a0.w;
            As[0][ac4 + 0][ar + 64] = a1.x; As[0][ac4 + 1][ar + 64] = a1.y;
            As[0][ac4 + 2][ar + 64] = a1.z; As[0][ac4 + 3][ar + 64] = a1.w;
            *(float4*)&Bs[0][wr][wc4] = w0;
            *(float4*)&Bs[0][wr + 8][wc4] = w1;
        }
        __syncthreads();

        int buf = 0;
        for (int k0 = 0; k0 < K; k0 += BK) {
            bool more = (k0 + BK) < K;
            float4 na0, na1, nw0, nw1;
            if (more) {
                int kn = k0 + BK;
                na0 = av0 ? *(const float4*)(Ap0 + kn + ac4) : f4z;
                na1 = av1 ? *(const float4*)(Ap1 + kn + ac4) : f4z;
                nw0 = *(const float4*)(W + (size_t)(kn + wr) * 256 + bcol + wc4);
                nw1 = *(const float4*)(W + (size_t)(kn + wr + 8) * 256 + bcol + wc4);
            }
#pragma unroll
            for (int k = 0; k < BK; k++) {
                float ra[8], rb[8];
#pragma unroll
                for (int i = 0; i < 8; i++) ra[i] = As[buf][k][ty * 8 + i];
#pragma unroll
                for (int j = 0; j < 8; j++) rb[j] = Bs[buf][k][tx * 8 + j];
#pragma unroll
                for (int i = 0; i < 8; i++)
#pragma unroll
                    for (int j = 0; j < 8; j++) acc[i][j] += ra[i] * rb[j];
            }
            if (more) {
                int nb = buf ^ 1;
                As[nb][ac4 + 0][ar] = na0.x; As[nb][ac4 + 1][ar] = na0.y;
                As[nb][ac4 + 2][ar] = na0.z; As[nb][ac4 + 3][ar] = na0.w;
                As[nb][ac4 + 0][ar + 64] = na1.x; As[nb][ac4 + 1][ar + 64] = na1.y;
                As[nb][ac4 + 2][ar + 64] = na1.z; As[nb][ac4 + 3][ar + 64] = na1.w;
                *(float4*)&Bs[nb][wr][wc4] = nw0;
                *(float4*)&Bs[nb][wr + 8][wc4] = nw1;
                __syncthreads();
            }
            buf ^= 1;
        }
    }

    // Epilogue
    float bb[8];
#pragma unroll
    for (int j = 0; j < 8; j++) bb[j] = bias ? bias[bcol + tx * 8 + j] : 0.f;

#pragma unroll
    for (int i = 0; i < 8; i++) {
        int r = brow + ty * 8 + i;
        if (r >= M) continue;
        size_t off = (size_t)r * 256 + bcol + tx * 8;
#pragma unroll
        for (int j = 0; j < 8; j++) {
            float v = acc[i][j] + bb[j];
            if (pre) v += pre[off + j];
            if (relu) v = fmaxf(v, 0.f);
            C[off + j] = v;
        }
    }
}

// ----------------------------------------------------------------------------
// Decoder: out[s] = dot(u[row[s]], g[col[s]]) over 256 dims. One warp per s.
// ----------------------------------------------------------------------------
__global__ void k_decode(const float* __restrict__ u, const float* __restrict__ g,
                         const int* __restrict__ rows, const int* __restrict__ cols,
                         float* __restrict__ out) {
    int w = (blockIdx.x * blockDim.x + threadIdx.x) >> 5;
    int lane = threadIdx.x & 31;
    if (w >= NS) return;
    const float4* ur = (const float4*)(u + (size_t)rows[w] * 256);
    const float4* gr = (const float4*)(g + (size_t)cols[w] * 256);
    float acc = 0.f;
#pragma unroll
    for (int i = 0; i < 2; i++) {
        float4 a = ur[lane + i * 32];
        float4 b = gr[lane + i * 32];
        acc += a.x * b.x + a.y * b.y + a.z * b.z + a.w * b.w;
    }
#pragma unroll
    for (int o = 16; o; o >>= 1) acc += __shfl_down_sync(0xffffffffu, acc, o);
    if (lane == 0) out[w] = acc;
}

// ----------------------------------------------------------------------------
// Host side
// ----------------------------------------------------------------------------
static void run_layer(const float* u_prev, int du, const float* g_prev, int dg,
                      const float* Wr_ug, const float* b_ug, const float* Wo_g,
                      const float* Wr_gu, const float* b_gu, const float* Wo_u,
                      float* g_out, float* u_out, int relu,
                      float* p_msg_g, float* p_y, float* p_msg_u,
                      int* p_rp_ug, int* p_es_ug, float* p_ws_ug,
                      int* p_rp_gu, int* p_es_gu, float* p_ws_gu) {
    // users -> games (direct form): msg_g[NG,du] = segsum_ug(u_prev)
    if (du == 128)
        k_segsum128<<<(NG + 7) / 8, 256>>>(u_prev, p_rp_ug, p_es_ug, p_ws_ug, p_msg_g, NG);
    else
        k_segsum256<<<(NG + 7) / 8, 256>>>(u_prev, p_rp_ug, p_es_ug, p_ws_ug, p_msg_g, NG);
    // g_out = relu?(msg_g@Wr_ug + g_prev@Wo_g + b_ug)
    k_gemm<<<dim3((NG + 127) / 128, 2), 256>>>(p_msg_g, Wr_ug, du,
                                               g_prev, Wo_g, dg,
                                               nullptr, b_ug, g_out, NG, relu);
    // games -> users (commuted form): y = g_prev@Wr_gu  [NG,256]
    k_gemm<<<dim3((NG + 127) / 128, 2), 256>>>(g_prev, Wr_gu, dg,
                                               nullptr, nullptr, 0,
                                               nullptr, nullptr, p_y, NG, 0);
    // msg_u[NU,256] = segsum_gu(y)
    k_segsum256<<<(NU + 7) / 8, 256>>>(p_y, p_rp_gu, p_es_gu, p_ws_gu, p_msg_u, NU);
    // u_out = relu?(msg_u + u_prev@Wo_u + b_gu)
    k_gemm<<<dim3((NU + 127) / 128, 2), 256>>>(u_prev, Wo_u, du,
                                               nullptr, nullptr, 0,
                                               p_msg_u, b_gu, u_out, NU, relu);
}

extern "C" void kernel_launch(void* const* d_in, const int* in_sizes, int n_in,
                              void* d_out, int out_size) {
    // ---- input mapping (handles both metadata orderings) ----
    const float *x_user, *x_game, *emb_game, *ew_ug, *ew_gu;
    const int *src_ug, *dst_ug, *src_gu, *dst_gu, *srow, *scol;
    const float *Wrug[3], *bug[3], *Wog[3], *Wrgu[3], *bgu[3], *Wou[3];

    x_user   = (const float*)d_in[0];
    x_game   = (const float*)d_in[1];
    emb_game = (const float*)d_in[2];
    ew_ug    = (const float*)d_in[3];
    ew_gu    = (const float*)d_in[4];

    if (in_sizes[5] == NE) {
        // setup_inputs dict order
        src_ug = (const int*)d_in[5];
        dst_ug = (const int*)d_in[6];
        src_gu = (const int*)d_in[7];
        dst_gu = (const int*)d_in[8];
        srow   = (const int*)d_in[9];
        scol   = (const int*)d_in[10];
        for (int l = 0; l < 3; l++) {
            int b = 11 + 6 * l;
            Wrug[l] = (const float*)d_in[b + 0];
            bug[l]  = (const float*)d_in[b + 1];
            Wog[l]  = (const float*)d_in[b + 2];
            Wrgu[l] = (const float*)d_in[b + 3];
            bgu[l]  = (const float*)d_in[b + 4];
            Wou[l]  = (const float*)d_in[b + 5];
        }
    } else {
        // reference signature order
        for (int l = 0; l < 3; l++) {
            int b = 5 + 6 * l;
            Wrug[l] = (const float*)d_in[b + 0];
            bug[l]  = (const float*)d_in[b + 1];
            Wog[l]  = (const float*)d_in[b + 2];
            Wrgu[l] = (const float*)d_in[b + 3];
            bgu[l]  = (const float*)d_in[b + 4];
            Wou[l]  = (const float*)d_in[b + 5];
        }
        src_ug = (const int*)d_in[23];
        dst_ug = (const int*)d_in[24];
        src_gu = (const int*)d_in[25];
        dst_gu = (const int*)d_in[26];
        srow   = (const int*)d_in[27];
        scol   = (const int*)d_in[28];
    }

    // ---- scratch symbol addresses ----
    float *p_xg, *p_u0, *p_u1, *p_g0, *p_g1, *p_msg_g, *p_y, *p_msg_u;
    float *p_ws_ug, *p_ws_gu;
    int *p_rp_ug, *p_rp_gu, *p_es_ug, *p_es_gu;
    cudaGetSymbolAddress((void**)&p_xg, d_xg);
    cudaGetSymbolAddress((void**)&p_u0, d_u0);
    cudaGetSymbolAddress((void**)&p_u1, d_u1);
    cudaGetSymbolAddress((void**)&p_g0, d_g0);
    cudaGetSymbolAddress((void**)&p_g1, d_g1);
    cudaGetSymbolAddress((void**)&p_msg_g, d_msg_g);
    cudaGetSymbolAddress((void**)&p_y, d_y);
    cudaGetSymbolAddress((void**)&p_msg_u, d_msg_u);
    cudaGetSymbolAddress((void**)&p_rp_ug, d_rp_ug);
    cudaGetSymbolAddress((void**)&p_rp_gu, d_rp_gu);
    cudaGetSymbolAddress((void**)&p_es_ug, d_es_ug);
    cudaGetSymbolAddress((void**)&p_es_gu, d_es_gu);
    cudaGetSymbolAddress((void**)&p_ws_ug, d_ws_ug);
    cudaGetSymbolAddress((void**)&p_ws_gu, d_ws_gu);

    float* out = (float*)d_out;

    // ---- setup: concat game features, build CSR (both directions) ----
    k_concat<<<(NG * 64 + 255) / 256, 256>>>(x_game, emb_game);
    k_zero_counts<<<(NU + 256) / 256, 256>>>();
    k_hist<<<(NE + 255) / 256, 256>>>(dst_ug, dst_gu);
    k_blocksum<<<dim3(98, 2), 256>>>();
    k_scanbsum<<<1, 32>>>();
    k_scanwrite<<<dim3(98, 2), 256>>>();
    k_cursor<<<(NU + 256) / 256, 256>>>();
    k_scatter<<<(NE + 255) / 256, 256>>>(src_ug, dst_ug, ew_ug,
                                         src_gu, dst_gu, ew_gu);

    // ---- 3 GraphConv layers ----
    run_layer(x_user, 128, p_xg, 128,
              Wrug[0], bug[0], Wog[0], Wrgu[0], bgu[0], Wou[0],
              p_g0, p_u0, 1,
              p_msg_g, p_y, p_msg_u,
              p_rp_ug, p_es_ug, p_ws_ug, p_rp_gu, p_es_gu, p_ws_gu);
    run_layer(p_u0, 256, p_g0, 256,
              Wrug[1], bug[1], Wog[1], Wrgu[1], bgu[1], Wou[1],
              p_g1, p_u1, 1,
              p_msg_g, p_y, p_msg_u,
              p_rp_ug, p_es_ug, p_ws_ug, p_rp_gu, p_es_gu, p_ws_gu);
    run_layer(p_u1, 256, p_g1, 256,
              Wrug[2], bug[2], Wog[2], Wrgu[2], bgu[2], Wou[2],
              p_g0, p_u0, 0,
              p_msg_g, p_y, p_msg_u,
              p_rp_ug, p_es_ug, p_ws_ug, p_rp_gu, p_es_gu, p_ws_gu);

    // ---- decoder ----
    k_decode<<<(NS * 32 + 255) / 256, 256>>>(p_u0, p_g0, srow, scol, out);
    (void)n_in; (void)out_size;
}

// round 14
// speedup vs baseline: 1.1594x; 1.0019x over previous
#include <cuda_runtime.h>
#include <cstdint>

#define NU 100000
#define NG 20000
#define NE 1000000
#define NS 500000
#define HH 256

// ----------------------------------------------------------------------------
// Static device scratch (no runtime allocation allowed)
// ----------------------------------------------------------------------------
__device__ float d_xg[NG * 128];          // concat(x_game, emb_game)
__device__ float d_u0[(size_t)NU * HH];
__device__ float d_u1[(size_t)NU * HH];
__device__ float d_g0[NG * HH];
__device__ float d_g1[NG * HH];
__device__ float d_msg_g[NG * HH];
__device__ float d_y[NG * HH];
__device__ float d_msg_u[(size_t)NU * HH];

__device__ int   d_rp_ug[NG + 1];
__device__ int   d_rp_gu[NU + 1];
__device__ int   d_cur_ug[NG + 1];
__device__ int   d_cur_gu[NU + 1];
__device__ int   d_es_ug[NE];
__device__ float d_ws_ug[NE];
__device__ int   d_es_gu[NE];
__device__ float d_ws_gu[NE];
__device__ int   d_bsum[256];             // per-1024-chunk sums (20 + 98 used)

// ----------------------------------------------------------------------------
// Setup kernels
// ----------------------------------------------------------------------------
__global__ void k_concat(const float* __restrict__ xg64, const float* __restrict__ emb) {
    int i = blockIdx.x * blockDim.x + threadIdx.x;   // over NG*64
    if (i < NG * 64) {
        int r = i >> 6, c = i & 63;
        d_xg[r * 128 + c]      = xg64[i];
        d_xg[r * 128 + 64 + c] = emb[i];
    }
}

__global__ void k_zero_counts() {
    int i = blockIdx.x * blockDim.x + threadIdx.x;
    if (i <= NG) d_cur_ug[i] = 0;
    if (i <= NU) d_cur_gu[i] = 0;
}

__global__ void k_hist(const int* __restrict__ dug, const int* __restrict__ dgu) {
    int e = blockIdx.x * blockDim.x + threadIdx.x;
    if (e < NE) {
        atomicAdd(&d_cur_ug[dug[e]], 1);
        atomicAdd(&d_cur_gu[dgu[e]], 1);
    }
}

// ---- 3-phase exclusive scan over the two count arrays -----------------------
// Phase A: per-1024-chunk sums. grid = (98, 2), block = 256.
__global__ void k_blocksum() {
    int which = blockIdx.y;
    int n = which ? NU : NG;
    const int* cnt = which ? d_cur_gu : d_cur_ug;
    int base = blockIdx.x * 1024;
    if (base >= n) return;
    int tid = threadIdx.x;
    int s = 0;
#pragma unroll
    for (int i = 0; i < 4; i++) {
        int idx = base + tid + i * 256;
        if (idx < n) s += cnt[idx];
    }
    __shared__ int ws[8];
    int lane = tid & 31, wid = tid >> 5;
#pragma unroll
    for (int o = 16; o; o >>= 1) s += __shfl_down_sync(0xffffffffu, s, o);
    if (lane == 0) ws[wid] = s;
    __syncthreads();
    if (tid == 0) {
        int t = 0;
#pragma unroll
        for (int i = 0; i < 8; i++) t += ws[i];
        d_bsum[which * 128 + blockIdx.x] = t;
    }
}

// Phase B: scan the (small) chunk-sum arrays; also writes rp[n] totals.
__global__ void k_scanbsum() {
    if (threadIdx.x == 0) {
        int run = 0;
        for (int i = 0; i < 20; i++) { int v = d_bsum[i]; d_bsum[i] = run; run += v; }
        d_rp_ug[NG] = run;
        run = 0;
        for (int i = 0; i < 98; i++) { int v = d_bsum[128 + i]; d_bsum[128 + i] = run; run += v; }
        d_rp_gu[NU] = run;
    }
}

// Phase C: per-chunk exclusive scan + chunk offset. grid = (98, 2), block = 256.
__global__ void k_scanwrite() {
    int which = blockIdx.y;
    int n = which ? NU : NG;
    const int* cnt = which ? d_cur_gu : d_cur_ug;
    int* rp = which ? d_rp_gu : d_rp_ug;
    int base = blockIdx.x * 1024;
    if (base >= n) return;
    int tid = threadIdx.x;

    int x[4];
#pragma unroll
    for (int i = 0; i < 4; i++) {
        int idx = base + tid * 4 + i;
        x[i] = (idx < n) ? cnt[idx] : 0;
    }
    int p[4];
    p[0] = 0; p[1] = x[0]; p[2] = p[1] + x[1]; p[3] = p[2] + x[2];
    int tsum = p[3] + x[3];

    __shared__ int ws[8];
    int lane = tid & 31, wid = tid >> 5;
    int v = tsum;
#pragma unroll
    for (int o = 1; o < 32; o <<= 1) {
        int t = __shfl_up_sync(0xffffffffu, v, o);
        if (lane >= o) v += t;
    }
    if (lane == 31) ws[wid] = v;
    __syncthreads();
    if (wid == 0) {
        int w = (lane < 8) ? ws[lane] : 0;
#pragma unroll
        for (int o = 1; o < 8; o <<= 1) {
            int t = __shfl_up_sync(0xffffffffu, w, o);
            if (lane >= o) w += t;
        }
        if (lane < 8) ws[lane] = w;
    }
    __syncthreads();
    int off = d_bsum[which * 128 + blockIdx.x] + (v - tsum) + (wid ? ws[wid - 1] : 0);
#pragma unroll
    for (int i = 0; i < 4; i++) {
        int idx = base + tid * 4 + i;
        if (idx < n) rp[idx] = off + p[i];
    }
}

__global__ void k_cursor() {
    int i = blockIdx.x * blockDim.x + threadIdx.x;
    if (i <= NG) d_cur_ug[i] = d_rp_ug[i];
    if (i <= NU) d_cur_gu[i] = d_rp_gu[i];
}

__global__ void k_scatter(const int* __restrict__ sug, const int* __restrict__ dug,
                          const float* __restrict__ wug,
                          const int* __restrict__ sgu, const int* __restrict__ dgu,
                          const float* __restrict__ wgu) {
    int e = blockIdx.x * blockDim.x + threadIdx.x;
    if (e < NE) {
        int p = atomicAdd(&d_cur_ug[dug[e]], 1);
        d_es_ug[p] = sug[e];
        d_ws_ug[p] = wug[e];
        int q = atomicAdd(&d_cur_gu[dgu[e]], 1);
        d_es_gu[q] = sgu[e];
        d_ws_gu[q] = wgu[e];
    }
}

// ----------------------------------------------------------------------------
// Segment sum, warp-per-row: out[row,:] = sum_j w_j * X[src_j,:]
// 8 warps per block, one CSR row per warp. Edge (src, w) broadcast via shfl.
// No shared memory, no barriers. D=256: lane owns cols [4l,4l+4) and
// [128+4l, 128+4l+4). D=128: lane owns cols [4l, 4l+4).
// ----------------------------------------------------------------------------
__global__ void k_segsum256(const float* __restrict__ X,
                            const int* __restrict__ rp,
                            const int* __restrict__ es,
                            const float* __restrict__ wv,
                            float* __restrict__ out, int nrows) {
    int row = blockIdx.x * 8 + (threadIdx.x >> 5);
    if (row >= nrows) return;
    int lane = threadIdx.x & 31;
    int beg = rp[row], end = rp[row + 1];

    float4 acc0 = make_float4(0.f, 0.f, 0.f, 0.f);
    float4 acc1 = make_float4(0.f, 0.f, 0.f, 0.f);

    for (int base = beg; base < end; base += 32) {
        int idx = base + lane;
        int   sj = (idx < end) ? es[idx] : 0;
        float wj = (idx < end) ? wv[idx] : 0.f;
        int cnt = min(32, end - base);
        for (int j = 0; j < cnt; j++) {
            int   s = __shfl_sync(0xffffffffu, sj, j);
            float w = __shfl_sync(0xffffffffu, wj, j);
            const float4* xr = (const float4*)(X + (size_t)s * 256);
            float4 x0 = xr[lane];
            float4 x1 = xr[lane + 32];
            acc0.x += w * x0.x; acc0.y += w * x0.y;
            acc0.z += w * x0.z; acc0.w += w * x0.w;
            acc1.x += w * x1.x; acc1.y += w * x1.y;
            acc1.z += w * x1.z; acc1.w += w * x1.w;
        }
    }
    float4* orow = (float4*)(out + (size_t)row * 256);
    orow[lane]      = acc0;
    orow[lane + 32] = acc1;
}

__global__ void k_segsum128(const float* __restrict__ X,
                            const int* __restrict__ rp,
                            const int* __restrict__ es,
                            const float* __restrict__ wv,
                            float* __restrict__ out, int nrows) {
    int row = blockIdx.x * 8 + (threadIdx.x >> 5);
    if (row >= nrows) return;
    int lane = threadIdx.x & 31;
    int beg = rp[row], end = rp[row + 1];

    float4 acc = make_float4(0.f, 0.f, 0.f, 0.f);

    for (int base = beg; base < end; base += 32) {
        int idx = base + lane;
        int   sj = (idx < end) ? es[idx] : 0;
        float wj = (idx < end) ? wv[idx] : 0.f;
        int cnt = min(32, end - base);
        for (int j = 0; j < cnt; j++) {
            int   s = __shfl_sync(0xffffffffu, sj, j);
            float w = __shfl_sync(0xffffffffu, wj, j);
            float4 x = ((const float4*)(X + (size_t)s * 128))[lane];
            acc.x += w * x.x; acc.y += w * x.y;
            acc.z += w * x.z; acc.w += w * x.w;
        }
    }
    ((float4*)(out + (size_t)row * 128))[lane] = acc;
}

// ----------------------------------------------------------------------------
// Fused SGEMM: C[M,256] = relu?( A1@W1 + (A2@W2)? + pre? + bias? )
// 128x128x16 tile, double-buffered smem, 256 threads, 8x8 microtile.
// Microkernel uses indexed smem reads (R11 form — ptxas vectorizes these;
// explicit float4 + register arrays regressed 300us in R12).
// ----------------------------------------------------------------------------
__global__ __launch_bounds__(256)
void k_gemm(const float* __restrict__ A1, const float* __restrict__ W1, int K1,
            const float* __restrict__ A2, const float* __restrict__ W2, int K2,
            const float* __restrict__ pre, const float* __restrict__ bias,
            float* __restrict__ C, int M, int relu) {
    constexpr int BM = 128, BN = 128, BK = 16;
    __shared__ float As[2][BK][BM + 4];
    __shared__ float Bs[2][BK][BN];

    int tid = threadIdx.x;
    int tx = tid & 15;        // 0..15  (cols)
    int ty = tid >> 4;        // 0..15  (rows)
    int brow = blockIdx.x * BM;
    int bcol = blockIdx.y * BN;

    float acc[8][8];
#pragma unroll
    for (int i = 0; i < 8; i++)
#pragma unroll
        for (int j = 0; j < 8; j++) acc[i][j] = 0.f;

    // A tile loader: 128x16 = 512 float4s; this thread loads rows ar, ar+64
    int ar  = tid >> 2;            // 0..63
    int ac4 = (tid & 3) * 4;       // 0,4,8,12
    int gr0 = brow + ar, gr1 = brow + ar + 64;
    bool av0 = (gr0 < M), av1 = (gr1 < M);
    int cr0 = av0 ? gr0 : (M - 1);
    int cr1 = av1 ? gr1 : (M - 1);
    // W tile loader: 16x128 = 512 float4s; rows wr, wr+8
    int wr  = tid >> 5;            // 0..7
    int wc4 = (tid & 31) * 4;      // 0..124

    const float4 f4z = make_float4(0.f, 0.f, 0.f, 0.f);

    for (int pass = 0; pass < 2; pass++) {
        const float* A = pass ? A2 : A1;
        const float* W = pass ? W2 : W1;
        int K = pass ? K2 : K1;
        if (A == nullptr) continue;
        const float* Ap0 = A + (size_t)cr0 * K;
        const float* Ap1 = A + (size_t)cr1 * K;

        // guard: previous pass's last compute must finish before reuse of buffers
        __syncthreads();

        // preload tile k0=0 into buffer 0
        {
            float4 a0 = av0 ? *(const float4*)(Ap0 + ac4) : f4z;
            float4 a1 = av1 ? *(const float4*)(Ap1 + ac4) : f4z;
            float4 w0 = *(const float4*)(W + (size_t)wr * 256 + bcol + wc4);
            float4 w1 = *(const float4*)(W + (size_t)(wr + 8) * 256 + bcol + wc4);
            As[0][ac4 + 0][ar] = a0.x; As[0][ac4 + 1][ar] = a0.y;
            As[0][ac4 + 2][ar] = a0.z; As[0][ac4 + 3][ar] = a0.w;
            As[0][ac4 + 0][ar + 64] = a1.x; As[0][ac4 + 1][ar + 64] = a1.y;
            As[0][ac4 + 2][ar + 64] = a1.z; As[0][ac4 + 3][ar + 64] = a1.w;
            *(float4*)&Bs[0][wr][wc4] = w0;
            *(float4*)&Bs[0][wr + 8][wc4] = w1;
        }
        __syncthreads();

        int buf = 0;
        for (int k0 = 0; k0 < K; k0 += BK) {
            bool more = (k0 + BK) < K;
            float4 na0, na1, nw0, nw1;
            if (more) {
                int kn = k0 + BK;
                na0 = av0 ? *(const float4*)(Ap0 + kn + ac4) : f4z;
                na1 = av1 ? *(const float4*)(Ap1 + kn + ac4) : f4z;
                nw0 = *(const float4*)(W + (size_t)(kn + wr) * 256 + bcol + wc4);
                nw1 = *(const float4*)(W + (size_t)(kn + wr + 8) * 256 + bcol + wc4);
            }
#pragma unroll
            for (int k = 0; k < BK; k++) {
                float ra[8], rb[8];
#pragma unroll
                for (int i = 0; i < 8; i++) ra[i] = As[buf][k][ty * 8 + i];
#pragma unroll
                for (int j = 0; j < 8; j++) rb[j] = Bs[buf][k][tx * 8 + j];
#pragma unroll
                for (int i = 0; i < 8; i++)
#pragma unroll
                    for (int j = 0; j < 8; j++) acc[i][j] += ra[i] * rb[j];
            }
            if (more) {
                int nb = buf ^ 1;
                As[nb][ac4 + 0][ar] = na0.x; As[nb][ac4 + 1][ar] = na0.y;
                As[nb][ac4 + 2][ar] = na0.z; As[nb][ac4 + 3][ar] = na0.w;
                As[nb][ac4 + 0][ar + 64] = na1.x; As[nb][ac4 + 1][ar + 64] = na1.y;
                As[nb][ac4 + 2][ar + 64] = na1.z; As[nb][ac4 + 3][ar + 64] = na1.w;
                *(float4*)&Bs[nb][wr][wc4] = nw0;
                *(float4*)&Bs[nb][wr + 8][wc4] = nw1;
                __syncthreads();
            }
            buf ^= 1;
        }
    }

    // Epilogue
    float bb[8];
#pragma unroll
    for (int j = 0; j < 8; j++) bb[j] = bias ? bias[bcol + tx * 8 + j] : 0.f;

#pragma unroll
    for (int i = 0; i < 8; i++) {
        int r = brow + ty * 8 + i;
        if (r >= M) continue;
        size_t off = (size_t)r * 256 + bcol + tx * 8;
#pragma unroll
        for (int j = 0; j < 8; j++) {
            float v = acc[i][j] + bb[j];
            if (pre) v += pre[off + j];
            if (relu) v = fmaxf(v, 0.f);
            C[off + j] = v;
        }
    }
}

// ----------------------------------------------------------------------------
// Decoder: out[s] = dot(u[row[s]], g[col[s]]) over 256 dims. One warp per s.
// ----------------------------------------------------------------------------
__global__ void k_decode(const float* __restrict__ u, const float* __restrict__ g,
                         const int* __restrict__ rows, const int* __restrict__ cols,
                         float* __restrict__ out) {
    int w = (blockIdx.x * blockDim.x + threadIdx.x) >> 5;
    int lane = threadIdx.x & 31;
    if (w >= NS) return;
    const float4* ur = (const float4*)(u + (size_t)rows[w] * 256);
    const float4* gr = (const float4*)(g + (size_t)cols[w] * 256);
    float acc = 0.f;
#pragma unroll
    for (int i = 0; i < 2; i++) {
        float4 a = ur[lane + i * 32];
        float4 b = gr[lane + i * 32];
        acc += a.x * b.x + a.y * b.y + a.z * b.z + a.w * b.w;
    }
#pragma unroll
    for (int o = 16; o; o >>= 1) acc += __shfl_down_sync(0xffffffffu, acc, o);
    if (lane == 0) out[w] = acc;
}

// ----------------------------------------------------------------------------
// Host side
// ----------------------------------------------------------------------------
static void run_layer(const float* u_prev, int du, const float* g_prev, int dg,
                      const float* Wr_ug, const float* b_ug, const float* Wo_g,
                      const float* Wr_gu, const float* b_gu, const float* Wo_u,
                      float* g_out, float* u_out, int relu,
                      float* p_msg_g, float* p_y, float* p_msg_u,
                      int* p_rp_ug, int* p_es_ug, float* p_ws_ug,
                      int* p_rp_gu, int* p_es_gu, float* p_ws_gu) {
    // users -> games (direct form): msg_g[NG,du] = segsum_ug(u_prev)
    if (du == 128)
        k_segsum128<<<(NG + 7) / 8, 256>>>(u_prev, p_rp_ug, p_es_ug, p_ws_ug, p_msg_g, NG);
    else
        k_segsum256<<<(NG + 7) / 8, 256>>>(u_prev, p_rp_ug, p_es_ug, p_ws_ug, p_msg_g, NG);
    // g_out = relu?(msg_g@Wr_ug + g_prev@Wo_g + b_ug)
    k_gemm<<<dim3((NG + 127) / 128, 2), 256>>>(p_msg_g, Wr_ug, du,
                                               g_prev, Wo_g, dg,
                                               nullptr, b_ug, g_out, NG, relu);
    // games -> users (commuted form): y = g_prev@Wr_gu  [NG,256]
    k_gemm<<<dim3((NG + 127) / 128, 2), 256>>>(g_prev, Wr_gu, dg,
                                               nullptr, nullptr, 0,
                                               nullptr, nullptr, p_y, NG, 0);
    // msg_u[NU,256] = segsum_gu(y)
    k_segsum256<<<(NU + 7) / 8, 256>>>(p_y, p_rp_gu, p_es_gu, p_ws_gu, p_msg_u, NU);
    // u_out = relu?(msg_u + u_prev@Wo_u + b_gu)
    k_gemm<<<dim3((NU + 127) / 128, 2), 256>>>(u_prev, Wo_u, du,
                                               nullptr, nullptr, 0,
                                               p_msg_u, b_gu, u_out, NU, relu);
}

extern "C" void kernel_launch(void* const* d_in, const int* in_sizes, int n_in,
                              void* d_out, int out_size) {
    // ---- input mapping (handles both metadata orderings) ----
    const float *x_user, *x_game, *emb_game, *ew_ug, *ew_gu;
    const int *src_ug, *dst_ug, *src_gu, *dst_gu, *srow, *scol;
    const float *Wrug[3], *bug[3], *Wog[3], *Wrgu[3], *bgu[3], *Wou[3];

    x_user   = (const float*)d_in[0];
    x_game   = (const float*)d_in[1];
    emb_game = (const float*)d_in[2];
    ew_ug    = (const float*)d_in[3];
    ew_gu    = (const float*)d_in[4];

    if (in_sizes[5] == NE) {
        // setup_inputs dict order
        src_ug = (const int*)d_in[5];
        dst_ug = (const int*)d_in[6];
        src_gu = (const int*)d_in[7];
        dst_gu = (const int*)d_in[8];
        srow   = (const int*)d_in[9];
        scol   = (const int*)d_in[10];
        for (int l = 0; l < 3; l++) {
            int b = 11 + 6 * l;
            Wrug[l] = (const float*)d_in[b + 0];
            bug[l]  = (const float*)d_in[b + 1];
            Wog[l]  = (const float*)d_in[b + 2];
            Wrgu[l] = (const float*)d_in[b + 3];
            bgu[l]  = (const float*)d_in[b + 4];
            Wou[l]  = (const float*)d_in[b + 5];
        }
    } else {
        // reference signature order
        for (int l = 0; l < 3; l++) {
            int b = 5 + 6 * l;
            Wrug[l] = (const float*)d_in[b + 0];
            bug[l]  = (const float*)d_in[b + 1];
            Wog[l]  = (const float*)d_in[b + 2];
            Wrgu[l] = (const float*)d_in[b + 3];
            bgu[l]  = (const float*)d_in[b + 4];
            Wou[l]  = (const float*)d_in[b + 5];
        }
        src_ug = (const int*)d_in[23];
        dst_ug = (const int*)d_in[24];
        src_gu = (const int*)d_in[25];
        dst_gu = (const int*)d_in[26];
        srow   = (const int*)d_in[27];
        scol   = (const int*)d_in[28];
    }

    // ---- scratch symbol addresses ----
    float *p_xg, *p_u0, *p_u1, *p_g0, *p_g1, *p_msg_g, *p_y, *p_msg_u;
    float *p_ws_ug, *p_ws_gu;
    int *p_rp_ug, *p_rp_gu, *p_es_ug, *p_es_gu;
    cudaGetSymbolAddress((void**)&p_xg, d_xg);
    cudaGetSymbolAddress((void**)&p_u0, d_u0);
    cudaGetSymbolAddress((void**)&p_u1, d_u1);
    cudaGetSymbolAddress((void**)&p_g0, d_g0);
    cudaGetSymbolAddress((void**)&p_g1, d_g1);
    cudaGetSymbolAddress((void**)&p_msg_g, d_msg_g);
    cudaGetSymbolAddress((void**)&p_y, d_y);
    cudaGetSymbolAddress((void**)&p_msg_u, d_msg_u);
    cudaGetSymbolAddress((void**)&p_rp_ug, d_rp_ug);
    cudaGetSymbolAddress((void**)&p_rp_gu, d_rp_gu);
    cudaGetSymbolAddress((void**)&p_es_ug, d_es_ug);
    cudaGetSymbolAddress((void**)&p_es_gu, d_es_gu);
    cudaGetSymbolAddress((void**)&p_ws_ug, d_ws_ug);
    cudaGetSymbolAddress((void**)&p_ws_gu, d_ws_gu);

    float* out = (float*)d_out;

    // ---- setup: concat game features, build CSR (both directions) ----
    k_concat<<<(NG * 64 + 255) / 256, 256>>>(x_game, emb_game);
    k_zero_counts<<<(NU + 256) / 256, 256>>>();
    k_hist<<<(NE + 255) / 256, 256>>>(dst_ug, dst_gu);
    k_blocksum<<<dim3(98, 2), 256>>>();
    k_scanbsum<<<1, 32>>>();
    k_scanwrite<<<dim3(98, 2), 256>>>();
    k_cursor<<<(NU + 256) / 256, 256>>>();
    k_scatter<<<(NE + 255) / 256, 256>>>(src_ug, dst_ug, ew_ug,
                                         src_gu, dst_gu, ew_gu);

    // ---- 3 GraphConv layers ----
    run_layer(x_user, 128, p_xg, 128,
              Wrug[0], bug[0], Wog[0], Wrgu[0], bgu[0], Wou[0],
              p_g0, p_u0, 1,
              p_msg_g, p_y, p_msg_u,
              p_rp_ug, p_es_ug, p_ws_ug, p_rp_gu, p_es_gu, p_ws_gu);
    run_layer(p_u0, 256, p_g0, 256,
              Wrug[1], bug[1], Wog[1], Wrgu[1], bgu[1], Wou[1],
              p_g1, p_u1, 1,
              p_msg_g, p_y, p_msg_u,
              p_rp_ug, p_es_ug, p_ws_ug, p_rp_gu, p_es_gu, p_ws_gu);
    run_layer(p_u1, 256, p_g1, 256,
              Wrug[2], bug[2], Wog[2], Wrgu[2], bgu[2], Wou[2],
              p_g0, p_u0, 0,
              p_msg_g, p_y, p_msg_u,
              p_rp_ug, p_es_ug, p_ws_ug, p_rp_gu, p_es_gu, p_ws_gu);

    // ---- decoder ----
    k_decode<<<(NS * 32 + 255) / 256, 256>>>(p_u0, p_g0, srow, scol, out);
    (void)n_in; (void)out_size;
}

// round 16
// speedup vs baseline: 1.8728x; 1.6153x over previous
#include <cuda_runtime.h>
#include <cuda_bf16.h>
#include <cstdint>

#define NU 100000
#define NG 20000
#define NE 1000000
#define NS 500000
#define HH 256

// ----------------------------------------------------------------------------
// Static device scratch (no runtime allocation allowed)
// ----------------------------------------------------------------------------
__device__ float d_xg[NG * 128];          // concat(x_game, emb_game)
__device__ float d_u0[(size_t)NU * HH];
__device__ float d_u1[(size_t)NU * HH];
__device__ float d_g0[NG * HH];
__device__ float d_g1[NG * HH];
__device__ float d_msg_g[NG * HH];
__device__ float d_y[NG * HH];
__device__ float d_msg_u[(size_t)NU * HH];

__device__ int   d_rp_ug[NG + 1];
__device__ int   d_rp_gu[NU + 1];
__device__ int   d_cur_ug[NG + 1];
__device__ int   d_cur_gu[NU + 1];
__device__ int   d_es_ug[NE];
__device__ float d_ws_ug[NE];
__device__ int   d_es_gu[NE];
__device__ float d_ws_gu[NE];
__device__ int   d_bsum[256];

// bf16 hi/lo weight scratch, transposed to [N=256, K] K-major. 4 slots/layer.
__device__ __nv_bfloat16 d_wh[4][256 * 256];
__device__ __nv_bfloat16 d_wl[4][256 * 256];

// ----------------------------------------------------------------------------
// Setup kernels
// ----------------------------------------------------------------------------
__global__ void k_concat(const float* __restrict__ xg64, const float* __restrict__ emb) {
    int i = blockIdx.x * blockDim.x + threadIdx.x;   // over NG*64
    if (i < NG * 64) {
        int r = i >> 6, c = i & 63;
        d_xg[r * 128 + c]      = xg64[i];
        d_xg[r * 128 + 64 + c] = emb[i];
    }
}

__global__ void k_zero_counts() {
    int i = blockIdx.x * blockDim.x + threadIdx.x;
    if (i <= NG) d_cur_ug[i] = 0;
    if (i <= NU) d_cur_gu[i] = 0;
}

__global__ void k_hist(const int* __restrict__ dug, const int* __restrict__ dgu) {
    int e = blockIdx.x * blockDim.x + threadIdx.x;
    if (e < NE) {
        atomicAdd(&d_cur_ug[dug[e]], 1);
        atomicAdd(&d_cur_gu[dgu[e]], 1);
    }
}

// ---- 3-phase exclusive scan over the two count arrays -----------------------
__global__ void k_blocksum() {
    int which = blockIdx.y;
    int n = which ? NU : NG;
    const int* cnt = which ? d_cur_gu : d_cur_ug;
    int base = blockIdx.x * 1024;
    if (base >= n) return;
    int tid = threadIdx.x;
    int s = 0;
#pragma unroll
    for (int i = 0; i < 4; i++) {
        int idx = base + tid + i * 256;
        if (idx < n) s += cnt[idx];
    }
    __shared__ int ws[8];
    int lane = tid & 31, wid = tid >> 5;
#pragma unroll
    for (int o = 16; o; o >>= 1) s += __shfl_down_sync(0xffffffffu, s, o);
    if (lane == 0) ws[wid] = s;
    __syncthreads();
    if (tid == 0) {
        int t = 0;
#pragma unroll
        for (int i = 0; i < 8; i++) t += ws[i];
        d_bsum[which * 128 + blockIdx.x] = t;
    }
}

__global__ void k_scanbsum() {
    if (threadIdx.x == 0) {
        int run = 0;
        for (int i = 0; i < 20; i++) { int v = d_bsum[i]; d_bsum[i] = run; run += v; }
        d_rp_ug[NG] = run;
        run = 0;
        for (int i = 0; i < 98; i++) { int v = d_bsum[128 + i]; d_bsum[128 + i] = run; run += v; }
        d_rp_gu[NU] = run;
    }
}

__global__ void k_scanwrite() {
    int which = blockIdx.y;
    int n = which ? NU : NG;
    const int* cnt = which ? d_cur_gu : d_cur_ug;
    int* rp = which ? d_rp_gu : d_rp_ug;
    int base = blockIdx.x * 1024;
    if (base >= n) return;
    int tid = threadIdx.x;

    int x[4];
#pragma unroll
    for (int i = 0; i < 4; i++) {
        int idx = base + tid * 4 + i;
        x[i] = (idx < n) ? cnt[idx] : 0;
    }
    int p[4];
    p[0] = 0; p[1] = x[0]; p[2] = p[1] + x[1]; p[3] = p[2] + x[2];
    int tsum = p[3] + x[3];

    __shared__ int ws[8];
    int lane = tid & 31, wid = tid >> 5;
    int v = tsum;
#pragma unroll
    for (int o = 1; o < 32; o <<= 1) {
        int t = __shfl_up_sync(0xffffffffu, v, o);
        if (lane >= o) v += t;
    }
    if (lane == 31) ws[wid] = v;
    __syncthreads();
    if (wid == 0) {
        int w = (lane < 8) ? ws[lane] : 0;
#pragma unroll
        for (int o = 1; o < 8; o <<= 1) {
            int t = __shfl_up_sync(0xffffffffu, w, o);
            if (lane >= o) w += t;
        }
        if (lane < 8) ws[lane] = w;
    }
    __syncthreads();
    int off = d_bsum[which * 128 + blockIdx.x] + (v - tsum) + (wid ? ws[wid - 1] : 0);
#pragma unroll
    for (int i = 0; i < 4; i++) {
        int idx = base + tid * 4 + i;
        if (idx < n) rp[idx] = off + p[i];
    }
}

__global__ void k_cursor() {
    int i = blockIdx.x * blockDim.x + threadIdx.x;
    if (i <= NG) d_cur_ug[i] = d_rp_ug[i];
    if (i <= NU) d_cur_gu[i] = d_rp_gu[i];
}

__global__ void k_scatter(const int* __restrict__ sug, const int* __restrict__ dug,
                          const float* __restrict__ wug,
                          const int* __restrict__ sgu, const int* __restrict__ dgu,
                          const float* __restrict__ wgu) {
    int e = blockIdx.x * blockDim.x + threadIdx.x;
    if (e < NE) {
        int p = atomicAdd(&d_cur_ug[dug[e]], 1);
        d_es_ug[p] = sug[e];
        d_ws_ug[p] = wug[e];
        int q = atomicAdd(&d_cur_gu[dgu[e]], 1);
        d_es_gu[q] = sgu[e];
        d_ws_gu[q] = wgu[e];
    }
}

// ----------------------------------------------------------------------------
// Segment sum, warp-per-row (unchanged from R14)
// ----------------------------------------------------------------------------
__global__ void k_segsum256(const float* __restrict__ X,
                            const int* __restrict__ rp,
                            const int* __restrict__ es,
                            const float* __restrict__ wv,
                            float* __restrict__ out, int nrows) {
    int row = blockIdx.x * 8 + (threadIdx.x >> 5);
    if (row >= nrows) return;
    int lane = threadIdx.x & 31;
    int beg = rp[row], end = rp[row + 1];

    float4 acc0 = make_float4(0.f, 0.f, 0.f, 0.f);
    float4 acc1 = make_float4(0.f, 0.f, 0.f, 0.f);

    for (int base = beg; base < end; base += 32) {
        int idx = base + lane;
        int   sj = (idx < end) ? es[idx] : 0;
        float wj = (idx < end) ? wv[idx] : 0.f;
        int cnt = min(32, end - base);
        for (int j = 0; j < cnt; j++) {
            int   s = __shfl_sync(0xffffffffu, sj, j);
            float w = __shfl_sync(0xffffffffu, wj, j);
            const float4* xr = (const float4*)(X + (size_t)s * 256);
            float4 x0 = xr[lane];
            float4 x1 = xr[lane + 32];
            acc0.x += w * x0.x; acc0.y += w * x0.y;
            acc0.z += w * x0.z; acc0.w += w * x0.w;
            acc1.x += w * x1.x; acc1.y += w * x1.y;
            acc1.z += w * x1.z; acc1.w += w * x1.w;
        }
    }
    float4* orow = (float4*)(out + (size_t)row * 256);
    orow[lane]      = acc0;
    orow[lane + 32] = acc1;
}

__global__ void k_segsum128(const float* __restrict__ X,
                            const int* __restrict__ rp,
                            const int* __restrict__ es,
                            const float* __restrict__ wv,
                            float* __restrict__ out, int nrows) {
    int row = blockIdx.x * 8 + (threadIdx.x >> 5);
    if (row >= nrows) return;
    int lane = threadIdx.x & 31;
    int beg = rp[row], end = rp[row + 1];

    float4 acc = make_float4(0.f, 0.f, 0.f, 0.f);

    for (int base = beg; base < end; base += 32) {
        int idx = base + lane;
        int   sj = (idx < end) ? es[idx] : 0;
        float wj = (idx < end) ? wv[idx] : 0.f;
        int cnt = min(32, end - base);
        for (int j = 0; j < cnt; j++) {
            int   s = __shfl_sync(0xffffffffu, sj, j);
            float w = __shfl_sync(0xffffffffu, wj, j);
            float4 x = ((const float4*)(X + (size_t)s * 128))[lane];
            acc.x += w * x.x; acc.y += w * x.y;
            acc.z += w * x.z; acc.w += w * x.w;
        }
    }
    ((float4*)(out + (size_t)row * 128))[lane] = acc;
}

// ----------------------------------------------------------------------------
// Weight split+transpose: Wt_hi/lo[n*K + k] = split(W[k*256 + n])
// ----------------------------------------------------------------------------
__global__ void k_wsplit(const float* __restrict__ W, int K,
                         __nv_bfloat16* __restrict__ oh,
                         __nv_bfloat16* __restrict__ ol) {
    int idx = blockIdx.x * 256 + threadIdx.x;
    if (idx >= 256 * K) return;
    int n = idx / K, k = idx - n * K;
    float w = W[k * 256 + n];
    __nv_bfloat16 h = __float2bfloat16(w);
    float l = w - __bfloat162float(h);
    oh[idx] = h;
    ol[idx] = __float2bfloat16(l);
}

// ----------------------------------------------------------------------------
// bf16x3 tensor-core GEMM via mma.sync (HMMA; legal under compute_103):
// C[M,256] = relu?(A1@W1 + (A2@W2)? + pre? + bias?)
// CTA tile 128x128 (grid.y=2), 8 warps, warp tile 32x64, BK=32.
// A split fp32->bf16 hi/lo during staging; B pre-split [256,K] K-major.
// acc += Ah*Bh + Ah*Bl + Al*Bh   (dropped Al*Bl term ~2^-18 relative)
// ----------------------------------------------------------------------------
__device__ __forceinline__ uint32_t bf2u(__nv_bfloat162 h) {
    return *reinterpret_cast<uint32_t*>(&h);
}

#define MMA_BF16(c, a, b0, b1)                                                 \
    asm volatile(                                                              \
        "mma.sync.aligned.m16n8k16.row.col.f32.bf16.bf16.f32 "                 \
        "{%0,%1,%2,%3}, {%4,%5,%6,%7}, {%8,%9}, {%0,%1,%2,%3};"                \
        : "+f"((c)[0]), "+f"((c)[1]), "+f"((c)[2]), "+f"((c)[3])               \
        : "r"((a)[0]), "r"((a)[1]), "r"((a)[2]), "r"((a)[3]),                  \
          "r"(b0), "r"(b1))

#define PITCH 40   // bf16 row pitch: 80 bytes = 20 banks -> conflict-free frags

__global__ __launch_bounds__(256)
void k_tgemm(const float* __restrict__ A1, const __nv_bfloat16* __restrict__ B1h,
             const __nv_bfloat16* __restrict__ B1l, int K1,
             const float* __restrict__ A2, const __nv_bfloat16* __restrict__ B2h,
             const __nv_bfloat16* __restrict__ B2l, int K2,
             const float* __restrict__ pre, const float* __restrict__ bias,
             float* __restrict__ C, int M, int relu) {
    __shared__ __nv_bfloat16 Ah[128][PITCH];
    __shared__ __nv_bfloat16 Al[128][PITCH];
    __shared__ __nv_bfloat16 Bh[128][PITCH];
    __shared__ __nv_bfloat16 Bl[128][PITCH];

    int tid = threadIdx.x, wid = tid >> 5, lane = tid & 31;
    int brow = blockIdx.x * 128;
    int bcol = blockIdx.y * 128;
    int wm = (wid >> 1) * 32;    // warp row offset within tile
    int wn = (wid & 1) * 64;     // warp col offset within tile

    float acc[2][8][4];
#pragma unroll
    for (int mt = 0; mt < 2; mt++)
#pragma unroll
        for (int nt = 0; nt < 8; nt++)
#pragma unroll
            for (int i = 0; i < 4; i++) acc[mt][nt][i] = 0.f;

    // staging mapping: thread covers row trow, k-halves tseg*16..+15
    int trow = tid >> 1;
    int tseg = tid & 1;
    int arow_c = min(brow + trow, M - 1);

    for (int pass = 0; pass < 2; pass++) {
        const float* A = pass ? A2 : A1;
        const __nv_bfloat16* Bhg = pass ? B2h : B1h;
        const __nv_bfloat16* Blg = pass ? B2l : B1l;
        int K = pass ? K2 : K1;
        if (A == nullptr) continue;
        const float* Arow = A + (size_t)arow_c * K;
        const __nv_bfloat16* Bhrow = Bhg + (size_t)(bcol + trow) * K;
        const __nv_bfloat16* Blrow = Blg + (size_t)(bcol + trow) * K;

        for (int k0 = 0; k0 < K; k0 += 32) {
            __syncthreads();   // previous compute done before smem overwrite
            // ---- stage A [128x32] fp32 -> hi/lo bf16 ----
#pragma unroll
            for (int i = 0; i < 4; i++) {
                int c = tseg * 16 + i * 4;
                float4 v = *(const float4*)(Arow + k0 + c);
                __nv_bfloat162 h01 = __floats2bfloat162_rn(v.x, v.y);
                __nv_bfloat162 h23 = __floats2bfloat162_rn(v.z, v.w);
                float l0 = v.x - __bfloat162float(h01.x);
                float l1 = v.y - __bfloat162float(h01.y);
                float l2 = v.z - __bfloat162float(h23.x);
                float l3 = v.w - __bfloat162float(h23.y);
                __nv_bfloat162 L01 = __floats2bfloat162_rn(l0, l1);
                __nv_bfloat162 L23 = __floats2bfloat162_rn(l2, l3);
                *(uint2*)&Ah[trow][c] = make_uint2(bf2u(h01), bf2u(h23));
                *(uint2*)&Al[trow][c] = make_uint2(bf2u(L01), bf2u(L23));
            }
            // ---- stage B [128x32] bf16 hi/lo (pre-split in gmem) ----
            {
                int c = tseg * 16;
                *(uint4*)&Bh[trow][c]     = *(const uint4*)(Bhrow + k0 + c);
                *(uint4*)&Bh[trow][c + 8] = *(const uint4*)(Bhrow + k0 + c + 8);
                *(uint4*)&Bl[trow][c]     = *(const uint4*)(Blrow + k0 + c);
                *(uint4*)&Bl[trow][c + 8] = *(const uint4*)(Blrow + k0 + c + 8);
            }
            __syncthreads();

            // ---- compute: 2 k16 steps ----
#pragma unroll
            for (int ks = 0; ks < 2; ks++) {
                int kb = ks * 16;
                int fr = lane >> 2;          // fragment row / col-n
                int fc = kb + (lane & 3) * 2;
                uint32_t ah[2][4], al[2][4];
#pragma unroll
                for (int mt = 0; mt < 2; mt++) {
                    int r = wm + mt * 16 + fr;
                    ah[mt][0] = *(const uint32_t*)&Ah[r][fc];
                    ah[mt][1] = *(const uint32_t*)&Ah[r + 8][fc];
                    ah[mt][2] = *(const uint32_t*)&Ah[r][fc + 8];
                    ah[mt][3] = *(const uint32_t*)&Ah[r + 8][fc + 8];
                    al[mt][0] = *(const uint32_t*)&Al[r][fc];
                    al[mt][1] = *(const uint32_t*)&Al[r + 8][fc];
                    al[mt][2] = *(const uint32_t*)&Al[r][fc + 8];
                    al[mt][3] = *(const uint32_t*)&Al[r + 8][fc + 8];
                }
#pragma unroll
                for (int nt = 0; nt < 8; nt++) {
                    int n = wn + nt * 8 + fr;
                    uint32_t bh0 = *(const uint32_t*)&Bh[n][fc];
                    uint32_t bh1 = *(const uint32_t*)&Bh[n][fc + 8];
                    uint32_t bl0 = *(const uint32_t*)&Bl[n][fc];
                    uint32_t bl1 = *(const uint32_t*)&Bl[n][fc + 8];
#pragma unroll
                    for (int mt = 0; mt < 2; mt++) {
                        MMA_BF16(acc[mt][nt], ah[mt], bh0, bh1);
                        MMA_BF16(acc[mt][nt], ah[mt], bl0, bl1);
                        MMA_BF16(acc[mt][nt], al[mt], bh0, bh1);
                    }
                }
            }
        }
    }

    // ---- epilogue ----
#pragma unroll
    for (int mt = 0; mt < 2; mt++) {
#pragma unroll
        for (int nt = 0; nt < 8; nt++) {
            int r0 = brow + wm + mt * 16 + (lane >> 2);
            int cb = bcol + wn + nt * 8 + (lane & 3) * 2;
            float b0 = bias ? bias[cb] : 0.f;
            float b1 = bias ? bias[cb + 1] : 0.f;
            if (r0 < M) {
                size_t o = (size_t)r0 * 256 + cb;
                float v0 = acc[mt][nt][0] + b0;
                float v1 = acc[mt][nt][1] + b1;
                if (pre) { v0 += pre[o]; v1 += pre[o + 1]; }
                if (relu) { v0 = fmaxf(v0, 0.f); v1 = fmaxf(v1, 0.f); }
                *(float2*)(C + o) = make_float2(v0, v1);
            }
            int r1 = r0 + 8;
            if (r1 < M) {
                size_t o = (size_t)r1 * 256 + cb;
                float v0 = acc[mt][nt][2] + b0;
                float v1 = acc[mt][nt][3] + b1;
                if (pre) { v0 += pre[o]; v1 += pre[o + 1]; }
                if (relu) { v0 = fmaxf(v0, 0.f); v1 = fmaxf(v1, 0.f); }
                *(float2*)(C + o) = make_float2(v0, v1);
            }
        }
    }
}

// ----------------------------------------------------------------------------
// Decoder: out[s] = dot(u[row[s]], g[col[s]]) over 256 dims. One warp per s.
// ----------------------------------------------------------------------------
__global__ void k_decode(const float* __restrict__ u, const float* __restrict__ g,
                         const int* __restrict__ rows, const int* __restrict__ cols,
                         float* __restrict__ out) {
    int w = (blockIdx.x * blockDim.x + threadIdx.x) >> 5;
    int lane = threadIdx.x & 31;
    if (w >= NS) return;
    const float4* ur = (const float4*)(u + (size_t)rows[w] * 256);
    const float4* gr = (const float4*)(g + (size_t)cols[w] * 256);
    float acc = 0.f;
#pragma unroll
    for (int i = 0; i < 2; i++) {
        float4 a = ur[lane + i * 32];
        float4 b = gr[lane + i * 32];
        acc += a.x * b.x + a.y * b.y + a.z * b.z + a.w * b.w;
    }
#pragma unroll
    for (int o = 16; o; o >>= 1) acc += __shfl_down_sync(0xffffffffu, acc, o);
    if (lane == 0) out[w] = acc;
}

// ----------------------------------------------------------------------------
// Host side
// ----------------------------------------------------------------------------
struct WSlots {
    __nv_bfloat16 *h[4], *l[4];
};

static void run_layer(const float* u_prev, int du, const float* g_prev, int dg,
                      const float* Wr_ug, const float* b_ug, const float* Wo_g,
                      const float* Wr_gu, const float* b_gu, const float* Wo_u,
                      float* g_out, float* u_out, int relu,
                      float* p_msg_g, float* p_y, float* p_msg_u,
                      int* p_rp_ug, int* p_es_ug, float* p_ws_ug,
                      int* p_rp_gu, int* p_es_gu, float* p_ws_gu,
                      const WSlots& ws) {
    // split+transpose this layer's weights into bf16 hi/lo slots
    k_wsplit<<<du, 256>>>(Wr_ug, du, ws.h[0], ws.l[0]);
    k_wsplit<<<dg, 256>>>(Wo_g,  dg, ws.h[1], ws.l[1]);
    k_wsplit<<<dg, 256>>>(Wr_gu, dg, ws.h[2], ws.l[2]);
    k_wsplit<<<du, 256>>>(Wo_u,  du, ws.h[3], ws.l[3]);

    // users -> games: msg_g[NG,du] = segsum_ug(u_prev)
    if (du == 128)
        k_segsum128<<<(NG + 7) / 8, 256>>>(u_prev, p_rp_ug, p_es_ug, p_ws_ug, p_msg_g, NG);
    else
        k_segsum256<<<(NG + 7) / 8, 256>>>(u_prev, p_rp_ug, p_es_ug, p_ws_ug, p_msg_g, NG);
    // g_out = relu?(msg_g@Wr_ug + g_prev@Wo_g + b_ug)
    k_tgemm<<<dim3((NG + 127) / 128, 2), 256>>>(p_msg_g, ws.h[0], ws.l[0], du,
                                                g_prev, ws.h[1], ws.l[1], dg,
                                                nullptr, b_ug, g_out, NG, relu);
    // games -> users (commuted): y = g_prev@Wr_gu
    k_tgemm<<<dim3((NG + 127) / 128, 2), 256>>>(g_prev, ws.h[2], ws.l[2], dg,
                                                nullptr, nullptr, nullptr, 0,
                                                nullptr, nullptr, p_y, NG, 0);
    // msg_u[NU,256] = segsum_gu(y)
    k_segsum256<<<(NU + 7) / 8, 256>>>(p_y, p_rp_gu, p_es_gu, p_ws_gu, p_msg_u, NU);
    // u_out = relu?(msg_u + u_prev@Wo_u + b_gu)
    k_tgemm<<<dim3((NU + 127) / 128, 2), 256>>>(u_prev, ws.h[3], ws.l[3], du,
                                                nullptr, nullptr, nullptr, 0,
                                                p_msg_u, b_gu, u_out, NU, relu);
}

extern "C" void kernel_launch(void* const* d_in, const int* in_sizes, int n_in,
                              void* d_out, int out_size) {
    // ---- input mapping (handles both metadata orderings) ----
    const float *x_user, *x_game, *emb_game, *ew_ug, *ew_gu;
    const int *src_ug, *dst_ug, *src_gu, *dst_gu, *srow, *scol;
    const float *Wrug[3], *bug[3], *Wog[3], *Wrgu[3], *bgu[3], *Wou[3];

    x_user   = (const float*)d_in[0];
    x_game   = (const float*)d_in[1];
    emb_game = (const float*)d_in[2];
    ew_ug    = (const float*)d_in[3];
    ew_gu    = (const float*)d_in[4];

    if (in_sizes[5] == NE) {
        src_ug = (const int*)d_in[5];
        dst_ug = (const int*)d_in[6];
        src_gu = (const int*)d_in[7];
        dst_gu = (const int*)d_in[8];
        srow   = (const int*)d_in[9];
        scol   = (const int*)d_in[10];
        for (int l = 0; l < 3; l++) {
            int b = 11 + 6 * l;
            Wrug[l] = (const float*)d_in[b + 0];
            bug[l]  = (const float*)d_in[b + 1];
            Wog[l]  = (const float*)d_in[b + 2];
            Wrgu[l] = (const float*)d_in[b + 3];
            bgu[l]  = (const float*)d_in[b + 4];
            Wou[l]  = (const float*)d_in[b + 5];
        }
    } else {
        for (int l = 0; l < 3; l++) {
            int b = 5 + 6 * l;
            Wrug[l] = (const float*)d_in[b + 0];
            bug[l]  = (const float*)d_in[b + 1];
            Wog[l]  = (const float*)d_in[b + 2];
            Wrgu[l] = (const float*)d_in[b + 3];
            bgu[l]  = (const float*)d_in[b + 4];
            Wou[l]  = (const float*)d_in[b + 5];
        }
        src_ug = (const int*)d_in[23];
        dst_ug = (const int*)d_in[24];
        src_gu = (const int*)d_in[25];
        dst_gu = (const int*)d_in[26];
        srow   = (const int*)d_in[27];
        scol   = (const int*)d_in[28];
    }

    // ---- scratch symbol addresses ----
    float *p_xg, *p_u0, *p_u1, *p_g0, *p_g1, *p_msg_g, *p_y, *p_msg_u;
    float *p_ws_ug, *p_ws_gu;
    int *p_rp_ug, *p_rp_gu, *p_es_ug, *p_es_gu;
    cudaGetSymbolAddress((void**)&p_xg, d_xg);
    cudaGetSymbolAddress((void**)&p_u0, d_u0);
    cudaGetSymbolAddress((void**)&p_u1, d_u1);
    cudaGetSymbolAddress((void**)&p_g0, d_g0);
    cudaGetSymbolAddress((void**)&p_g1, d_g1);
    cudaGetSymbolAddress((void**)&p_msg_g, d_msg_g);
    cudaGetSymbolAddress((void**)&p_y, d_y);
    cudaGetSymbolAddress((void**)&p_msg_u, d_msg_u);
    cudaGetSymbolAddress((void**)&p_rp_ug, d_rp_ug);
    cudaGetSymbolAddress((void**)&p_rp_gu, d_rp_gu);
    cudaGetSymbolAddress((void**)&p_es_ug, d_es_ug);
    cudaGetSymbolAddress((void**)&p_es_gu, d_es_gu);
    cudaGetSymbolAddress((void**)&p_ws_ug, d_ws_ug);
    cudaGetSymbolAddress((void**)&p_ws_gu, d_ws_gu);

    WSlots ws;
    {
        __nv_bfloat16* base_h;
        __nv_bfloat16* base_l;
        cudaGetSymbolAddress((void**)&base_h, d_wh);
        cudaGetSymbolAddress((void**)&base_l, d_wl);
        for (int s = 0; s < 4; s++) {
            ws.h[s] = base_h + (size_t)s * 256 * 256;
            ws.l[s] = base_l + (size_t)s * 256 * 256;
        }
    }

    float* out = (float*)d_out;

    // ---- setup: concat game features, build CSR (both directions) ----
    k_concat<<<(NG * 64 + 255) / 256, 256>>>(x_game, emb_game);
    k_zero_counts<<<(NU + 256) / 256, 256>>>();
    k_hist<<<(NE + 255) / 256, 256>>>(dst_ug, dst_gu);
    k_blocksum<<<dim3(98, 2), 256>>>();
    k_scanbsum<<<1, 32>>>();
    k_scanwrite<<<dim3(98, 2), 256>>>();
    k_cursor<<<(NU + 256) / 256, 256>>>();
    k_scatter<<<(NE + 255) / 256, 256>>>(src_ug, dst_ug, ew_ug,
                                         src_gu, dst_gu, ew_gu);

    // ---- 3 GraphConv layers ----
    run_layer(x_user, 128, p_xg, 128,
              Wrug[0], bug[0], Wog[0], Wrgu[0], bgu[0], Wou[0],
              p_g0, p_u0, 1,
              p_msg_g, p_y, p_msg_u,
              p_rp_ug, p_es_ug, p_ws_ug, p_rp_gu, p_es_gu, p_ws_gu, ws);
    run_layer(p_u0, 256, p_g0, 256,
              Wrug[1], bug[1], Wog[1], Wrgu[1], bgu[1], Wou[1],
              p_g1, p_u1, 1,
              p_msg_g, p_y, p_msg_u,
              p_rp_ug, p_es_ug, p_ws_ug, p_rp_gu, p_es_gu, p_ws_gu, ws);
    run_layer(p_u1, 256, p_g1, 256,
              Wrug[2], bug[2], Wog[2], Wrgu[2], bgu[2], Wou[2],
              p_g0, p_u0, 0,
              p_msg_g, p_y, p_msg_u,
              p_rp_ug, p_es_ug, p_ws_ug, p_rp_gu, p_es_gu, p_ws_gu, ws);

    // ---- decoder ----
    k_decode<<<(NS * 32 + 255) / 256, 256>>>(p_u0, p_g0, srow, scol, out);
    (void)n_in; (void)out_size;
}

// round 17
// speedup vs baseline: 2.0291x; 1.0835x over previous
#include <cuda_runtime.h>
#include <cuda_bf16.h>
#include <cstdint>

#define NU 100000
#define NG 20000
#define NE 1000000
#define NS 500000
#define HH 256

// ----------------------------------------------------------------------------
// Static device scratch (no runtime allocation allowed)
// ----------------------------------------------------------------------------
__device__ float d_xg[NG * 128];          // concat(x_game, emb_game)
__device__ float d_u0[(size_t)NU * HH];
__device__ float d_u1[(size_t)NU * HH];
__device__ float d_g0[NG * HH];
__device__ float d_g1[NG * HH];
__device__ float d_msg_g[NG * HH];
__device__ float d_y[NG * HH];
__device__ float d_msg_u[(size_t)NU * HH];

__device__ int   d_rp_ug[NG + 1];
__device__ int   d_rp_gu[NU + 1];
__device__ int   d_cur_ug[NG + 1];
__device__ int   d_cur_gu[NU + 1];
__device__ int   d_es_ug[NE];
__device__ float d_ws_ug[NE];
__device__ int   d_es_gu[NE];
__device__ float d_ws_gu[NE];
__device__ int   d_bsum[256];

// bf16 hi/lo weight scratch, transposed to [N=256, K] K-major. 12 slots
// (4 per layer x 3 layers), all split up-front in one kernel.
__device__ __nv_bfloat16 d_wh[12][256 * 256];
__device__ __nv_bfloat16 d_wl[12][256 * 256];

// ----------------------------------------------------------------------------
// Setup kernels
// ----------------------------------------------------------------------------
__global__ void k_concat(const float* __restrict__ xg64, const float* __restrict__ emb) {
    int i = blockIdx.x * blockDim.x + threadIdx.x;   // over NG*64
    if (i < NG * 64) {
        int r = i >> 6, c = i & 63;
        d_xg[r * 128 + c]      = xg64[i];
        d_xg[r * 128 + 64 + c] = emb[i];
    }
}

__global__ void k_zero_counts() {
    int i = blockIdx.x * blockDim.x + threadIdx.x;
    if (i <= NG) d_cur_ug[i] = 0;
    if (i <= NU) d_cur_gu[i] = 0;
}

__global__ void k_hist(const int* __restrict__ dug, const int* __restrict__ dgu) {
    int e = blockIdx.x * blockDim.x + threadIdx.x;
    if (e < NE) {
        atomicAdd(&d_cur_ug[dug[e]], 1);
        atomicAdd(&d_cur_gu[dgu[e]], 1);
    }
}

// ---- 3-phase exclusive scan over the two count arrays -----------------------
__global__ void k_blocksum() {
    int which = blockIdx.y;
    int n = which ? NU : NG;
    const int* cnt = which ? d_cur_gu : d_cur_ug;
    int base = blockIdx.x * 1024;
    if (base >= n) return;
    int tid = threadIdx.x;
    int s = 0;
#pragma unroll
    for (int i = 0; i < 4; i++) {
        int idx = base + tid + i * 256;
        if (idx < n) s += cnt[idx];
    }
    __shared__ int ws[8];
    int lane = tid & 31, wid = tid >> 5;
#pragma unroll
    for (int o = 16; o; o >>= 1) s += __shfl_down_sync(0xffffffffu, s, o);
    if (lane == 0) ws[wid] = s;
    __syncthreads();
    if (tid == 0) {
        int t = 0;
#pragma unroll
        for (int i = 0; i < 8; i++) t += ws[i];
        d_bsum[which * 128 + blockIdx.x] = t;
    }
}

__global__ void k_scanbsum() {
    if (threadIdx.x == 0) {
        int run = 0;
        for (int i = 0; i < 20; i++) { int v = d_bsum[i]; d_bsum[i] = run; run += v; }
        d_rp_ug[NG] = run;
        run = 0;
        for (int i = 0; i < 98; i++) { int v = d_bsum[128 + i]; d_bsum[128 + i] = run; run += v; }
        d_rp_gu[NU] = run;
    }
}

__global__ void k_scanwrite() {
    int which = blockIdx.y;
    int n = which ? NU : NG;
    const int* cnt = which ? d_cur_gu : d_cur_ug;
    int* rp = which ? d_rp_gu : d_rp_ug;
    int base = blockIdx.x * 1024;
    if (base >= n) return;
    int tid = threadIdx.x;

    int x[4];
#pragma unroll
    for (int i = 0; i < 4; i++) {
        int idx = base + tid * 4 + i;
        x[i] = (idx < n) ? cnt[idx] : 0;
    }
    int p[4];
    p[0] = 0; p[1] = x[0]; p[2] = p[1] + x[1]; p[3] = p[2] + x[2];
    int tsum = p[3] + x[3];

    __shared__ int ws[8];
    int lane = tid & 31, wid = tid >> 5;
    int v = tsum;
#pragma unroll
    for (int o = 1; o < 32; o <<= 1) {
        int t = __shfl_up_sync(0xffffffffu, v, o);
        if (lane >= o) v += t;
    }
    if (lane == 31) ws[wid] = v;
    __syncthreads();
    if (wid == 0) {
        int w = (lane < 8) ? ws[lane] : 0;
#pragma unroll
        for (int o = 1; o < 8; o <<= 1) {
            int t = __shfl_up_sync(0xffffffffu, w, o);
            if (lane >= o) w += t;
        }
        if (lane < 8) ws[lane] = w;
    }
    __syncthreads();
    int off = d_bsum[which * 128 + blockIdx.x] + (v - tsum) + (wid ? ws[wid - 1] : 0);
#pragma unroll
    for (int i = 0; i < 4; i++) {
        int idx = base + tid * 4 + i;
        if (idx < n) rp[idx] = off + p[i];
    }
}

__global__ void k_cursor() {
    int i = blockIdx.x * blockDim.x + threadIdx.x;
    if (i <= NG) d_cur_ug[i] = d_rp_ug[i];
    if (i <= NU) d_cur_gu[i] = d_rp_gu[i];
}

__global__ void k_scatter(const int* __restrict__ sug, const int* __restrict__ dug,
                          const float* __restrict__ wug,
                          const int* __restrict__ sgu, const int* __restrict__ dgu,
                          const float* __restrict__ wgu) {
    int e = blockIdx.x * blockDim.x + threadIdx.x;
    if (e < NE) {
        int p = atomicAdd(&d_cur_ug[dug[e]], 1);
        d_es_ug[p] = sug[e];
        d_ws_ug[p] = wug[e];
        int q = atomicAdd(&d_cur_gu[dgu[e]], 1);
        d_es_gu[q] = sgu[e];
        d_ws_gu[q] = wgu[e];
    }
}

// ----------------------------------------------------------------------------
// Segment sum, warp-per-row, edge loop unrolled x2 for MLP.
// ----------------------------------------------------------------------------
__global__ void k_segsum256(const float* __restrict__ X,
                            const int* __restrict__ rp,
                            const int* __restrict__ es,
                            const float* __restrict__ wv,
                            float* __restrict__ out, int nrows) {
    int row = blockIdx.x * 8 + (threadIdx.x >> 5);
    if (row >= nrows) return;
    int lane = threadIdx.x & 31;
    int beg = rp[row], end = rp[row + 1];

    float4 acc0 = make_float4(0.f, 0.f, 0.f, 0.f);
    float4 acc1 = make_float4(0.f, 0.f, 0.f, 0.f);

    for (int base = beg; base < end; base += 32) {
        int idx = base + lane;
        int   sj = (idx < end) ? es[idx] : 0;
        float wj = (idx < end) ? wv[idx] : 0.f;
        int cnt = min(32, end - base);
        int j = 0;
        for (; j + 2 <= cnt; j += 2) {
            int   s0 = __shfl_sync(0xffffffffu, sj, j);
            int   s1 = __shfl_sync(0xffffffffu, sj, j + 1);
            float w0 = __shfl_sync(0xffffffffu, wj, j);
            float w1 = __shfl_sync(0xffffffffu, wj, j + 1);
            const float4* xr0 = (const float4*)(X + (size_t)s0 * 256);
            const float4* xr1 = (const float4*)(X + (size_t)s1 * 256);
            float4 a0 = xr0[lane];
            float4 a1 = xr0[lane + 32];
            float4 b0 = xr1[lane];
            float4 b1 = xr1[lane + 32];
            acc0.x += w0 * a0.x; acc0.y += w0 * a0.y;
            acc0.z += w0 * a0.z; acc0.w += w0 * a0.w;
            acc1.x += w0 * a1.x; acc1.y += w0 * a1.y;
            acc1.z += w0 * a1.z; acc1.w += w0 * a1.w;
            acc0.x += w1 * b0.x; acc0.y += w1 * b0.y;
            acc0.z += w1 * b0.z; acc0.w += w1 * b0.w;
            acc1.x += w1 * b1.x; acc1.y += w1 * b1.y;
            acc1.z += w1 * b1.z; acc1.w += w1 * b1.w;
        }
        if (j < cnt) {
            int   s = __shfl_sync(0xffffffffu, sj, j);
            float w = __shfl_sync(0xffffffffu, wj, j);
            const float4* xr = (const float4*)(X + (size_t)s * 256);
            float4 x0 = xr[lane];
            float4 x1 = xr[lane + 32];
            acc0.x += w * x0.x; acc0.y += w * x0.y;
            acc0.z += w * x0.z; acc0.w += w * x0.w;
            acc1.x += w * x1.x; acc1.y += w * x1.y;
            acc1.z += w * x1.z; acc1.w += w * x1.w;
        }
    }
    float4* orow = (float4*)(out + (size_t)row * 256);
    orow[lane]      = acc0;
    orow[lane + 32] = acc1;
}

__global__ void k_segsum128(const float* __restrict__ X,
                            const int* __restrict__ rp,
                            const int* __restrict__ es,
                            const float* __restrict__ wv,
                            float* __restrict__ out, int nrows) {
    int row = blockIdx.x * 8 + (threadIdx.x >> 5);
    if (row >= nrows) return;
    int lane = threadIdx.x & 31;
    int beg = rp[row], end = rp[row + 1];

    float4 acc = make_float4(0.f, 0.f, 0.f, 0.f);

    for (int base = beg; base < end; base += 32) {
        int idx = base + lane;
        int   sj = (idx < end) ? es[idx] : 0;
        float wj = (idx < end) ? wv[idx] : 0.f;
        int cnt = min(32, end - base);
        int j = 0;
        for (; j + 2 <= cnt; j += 2) {
            int   s0 = __shfl_sync(0xffffffffu, sj, j);
            int   s1 = __shfl_sync(0xffffffffu, sj, j + 1);
            float w0 = __shfl_sync(0xffffffffu, wj, j);
            float w1 = __shfl_sync(0xffffffffu, wj, j + 1);
            float4 a = ((const float4*)(X + (size_t)s0 * 128))[lane];
            float4 b = ((const float4*)(X + (size_t)s1 * 128))[lane];
            acc.x += w0 * a.x; acc.y += w0 * a.y;
            acc.z += w0 * a.z; acc.w += w0 * a.w;
            acc.x += w1 * b.x; acc.y += w1 * b.y;
            acc.z += w1 * b.z; acc.w += w1 * b.w;
        }
        if (j < cnt) {
            int   s = __shfl_sync(0xffffffffu, sj, j);
            float w = __shfl_sync(0xffffffffu, wj, j);
            float4 x = ((const float4*)(X + (size_t)s * 128))[lane];
            acc.x += w * x.x; acc.y += w * x.y;
            acc.z += w * x.z; acc.w += w * x.w;
        }
    }
    ((float4*)(out + (size_t)row * 128))[lane] = acc;
}

// ----------------------------------------------------------------------------
// Batched weight split+transpose: all 12 slots in one kernel.
// slot s: Wt_hi/lo[s][n*K + k] = split(W_s[k*256 + n])
// ----------------------------------------------------------------------------
struct WSplitArgs {
    const float* W[12];
    int K[12];
};

__global__ void k_wsplit_all(WSplitArgs args) {
    int slot = blockIdx.y;
    int K = args.K[slot];
    int idx = blockIdx.x * 256 + threadIdx.x;
    if (idx >= 256 * K) return;
    const float* W = args.W[slot];
    int n = idx / K, k = idx - n * K;
    float w = W[k * 256 + n];
    __nv_bfloat16 h = __float2bfloat16(w);
    float l = w - __bfloat162float(h);
    d_wh[slot][idx] = h;
    d_wl[slot][idx] = __float2bfloat16(l);
}

// ----------------------------------------------------------------------------
// bf16x3 tensor-core GEMM via mma.sync (HMMA; legal under compute_103):
// C[M,256] = relu?(A1@W1 + (A2@W2)? + pre? + bias?)
// CTA tile 128x128 (grid.y=2), 8 warps, warp tile 32x64, BK=32.
// ----------------------------------------------------------------------------
__device__ __forceinline__ uint32_t bf2u(__nv_bfloat162 h) {
    return *reinterpret_cast<uint32_t*>(&h);
}

#define MMA_BF16(c, a, b0, b1)                                                 \
    asm volatile(                                                              \
        "mma.sync.aligned.m16n8k16.row.col.f32.bf16.bf16.f32 "                 \
        "{%0,%1,%2,%3}, {%4,%5,%6,%7}, {%8,%9}, {%0,%1,%2,%3};"                \
        : "+f"((c)[0]), "+f"((c)[1]), "+f"((c)[2]), "+f"((c)[3])               \
        : "r"((a)[0]), "r"((a)[1]), "r"((a)[2]), "r"((a)[3]),                  \
          "r"(b0), "r"(b1))

#define PITCH 40   // bf16 row pitch: 80 bytes = 20 banks -> conflict-free frags

__global__ __launch_bounds__(256)
void k_tgemm(const float* __restrict__ A1, const __nv_bfloat16* __restrict__ B1h,
             const __nv_bfloat16* __restrict__ B1l, int K1,
             const float* __restrict__ A2, const __nv_bfloat16* __restrict__ B2h,
             const __nv_bfloat16* __restrict__ B2l, int K2,
             const float* __restrict__ pre, const float* __restrict__ bias,
             float* __restrict__ C, int M, int relu) {
    __shared__ __nv_bfloat16 Ah[128][PITCH];
    __shared__ __nv_bfloat16 Al[128][PITCH];
    __shared__ __nv_bfloat16 Bh[128][PITCH];
    __shared__ __nv_bfloat16 Bl[128][PITCH];

    int tid = threadIdx.x, wid = tid >> 5, lane = tid & 31;
    int brow = blockIdx.x * 128;
    int bcol = blockIdx.y * 128;
    int wm = (wid >> 1) * 32;    // warp row offset within tile
    int wn = (wid & 1) * 64;     // warp col offset within tile

    float acc[2][8][4];
#pragma unroll
    for (int mt = 0; mt < 2; mt++)
#pragma unroll
        for (int nt = 0; nt < 8; nt++)
#pragma unroll
            for (int i = 0; i < 4; i++) acc[mt][nt][i] = 0.f;

    // staging mapping: thread covers row trow, k-halves tseg*16..+15
    int trow = tid >> 1;
    int tseg = tid & 1;
    int arow_c = min(brow + trow, M - 1);

    for (int pass = 0; pass < 2; pass++) {
        const float* A = pass ? A2 : A1;
        const __nv_bfloat16* Bhg = pass ? B2h : B1h;
        const __nv_bfloat16* Blg = pass ? B2l : B1l;
        int K = pass ? K2 : K1;
        if (A == nullptr) continue;
        const float* Arow = A + (size_t)arow_c * K;
        const __nv_bfloat16* Bhrow = Bhg + (size_t)(bcol + trow) * K;
        const __nv_bfloat16* Blrow = Blg + (size_t)(bcol + trow) * K;

        for (int k0 = 0; k0 < K; k0 += 32) {
            __syncthreads();   // previous compute done before smem overwrite
            // ---- stage A [128x32] fp32 -> hi/lo bf16 ----
#pragma unroll
            for (int i = 0; i < 4; i++) {
                int c = tseg * 16 + i * 4;
                float4 v = *(const float4*)(Arow + k0 + c);
                __nv_bfloat162 h01 = __floats2bfloat162_rn(v.x, v.y);
                __nv_bfloat162 h23 = __floats2bfloat162_rn(v.z, v.w);
                float l0 = v.x - __bfloat162float(h01.x);
                float l1 = v.y - __bfloat162float(h01.y);
                float l2 = v.z - __bfloat162float(h23.x);
                float l3 = v.w - __bfloat162float(h23.y);
                __nv_bfloat162 L01 = __floats2bfloat162_rn(l0, l1);
                __nv_bfloat162 L23 = __floats2bfloat162_rn(l2, l3);
                *(uint2*)&Ah[trow][c] = make_uint2(bf2u(h01), bf2u(h23));
                *(uint2*)&Al[trow][c] = make_uint2(bf2u(L01), bf2u(L23));
            }
            // ---- stage B [128x32] bf16 hi/lo (pre-split in gmem) ----
            {
                int c = tseg * 16;
                *(uint4*)&Bh[trow][c]     = *(const uint4*)(Bhrow + k0 + c);
                *(uint4*)&Bh[trow][c + 8] = *(const uint4*)(Bhrow + k0 + c + 8);
                *(uint4*)&Bl[trow][c]     = *(const uint4*)(Blrow + k0 + c);
                *(uint4*)&Bl[trow][c + 8] = *(const uint4*)(Blrow + k0 + c + 8);
            }
            __syncthreads();

            // ---- compute: 2 k16 steps ----
#pragma unroll
            for (int ks = 0; ks < 2; ks++) {
                int kb = ks * 16;
                int fr = lane >> 2;          // fragment row / col-n
                int fc = kb + (lane & 3) * 2;
                uint32_t ah[2][4], al[2][4];
#pragma unroll
                for (int mt = 0; mt < 2; mt++) {
                    int r = wm + mt * 16 + fr;
                    ah[mt][0] = *(const uint32_t*)&Ah[r][fc];
                    ah[mt][1] = *(const uint32_t*)&Ah[r + 8][fc];
                    ah[mt][2] = *(const uint32_t*)&Ah[r][fc + 8];
                    ah[mt][3] = *(const uint32_t*)&Ah[r + 8][fc + 8];
                    al[mt][0] = *(const uint32_t*)&Al[r][fc];
                    al[mt][1] = *(const uint32_t*)&Al[r + 8][fc];
                    al[mt][2] = *(const uint32_t*)&Al[r][fc + 8];
                    al[mt][3] = *(const uint32_t*)&Al[r + 8][fc + 8];
                }
#pragma unroll
                for (int nt = 0; nt < 8; nt++) {
                    int n = wn + nt * 8 + fr;
                    uint32_t bh0 = *(const uint32_t*)&Bh[n][fc];
                    uint32_t bh1 = *(const uint32_t*)&Bh[n][fc + 8];
                    uint32_t bl0 = *(const uint32_t*)&Bl[n][fc];
                    uint32_t bl1 = *(const uint32_t*)&Bl[n][fc + 8];
#pragma unroll
                    for (int mt = 0; mt < 2; mt++) {
                        MMA_BF16(acc[mt][nt], ah[mt], bh0, bh1);
                        MMA_BF16(acc[mt][nt], ah[mt], bl0, bl1);
                        MMA_BF16(acc[mt][nt], al[mt], bh0, bh1);
                    }
                }
            }
        }
    }

    // ---- epilogue ----
#pragma unroll
    for (int mt = 0; mt < 2; mt++) {
#pragma unroll
        for (int nt = 0; nt < 8; nt++) {
            int r0 = brow + wm + mt * 16 + (lane >> 2);
            int cb = bcol + wn + nt * 8 + (lane & 3) * 2;
            float b0 = bias ? bias[cb] : 0.f;
            float b1 = bias ? bias[cb + 1] : 0.f;
            if (r0 < M) {
                size_t o = (size_t)r0 * 256 + cb;
                float v0 = acc[mt][nt][0] + b0;
                float v1 = acc[mt][nt][1] + b1;
                if (pre) {
                    float2 p = *(const float2*)(pre + o);
                    v0 += p.x; v1 += p.y;
                }
                if (relu) { v0 = fmaxf(v0, 0.f); v1 = fmaxf(v1, 0.f); }
                *(float2*)(C + o) = make_float2(v0, v1);
            }
            int r1 = r0 + 8;
            if (r1 < M) {
                size_t o = (size_t)r1 * 256 + cb;
                float v0 = acc[mt][nt][2] + b0;
                float v1 = acc[mt][nt][3] + b1;
                if (pre) {
                    float2 p = *(const float2*)(pre + o);
                    v0 += p.x; v1 += p.y;
                }
                if (relu) { v0 = fmaxf(v0, 0.f); v1 = fmaxf(v1, 0.f); }
                *(float2*)(C + o) = make_float2(v0, v1);
            }
        }
    }
}

// ----------------------------------------------------------------------------
// Decoder: out[s] = dot(u[row[s]], g[col[s]]) over 256 dims. One warp per s.
// ----------------------------------------------------------------------------
__global__ void k_decode(const float* __restrict__ u, const float* __restrict__ g,
                         const int* __restrict__ rows, const int* __restrict__ cols,
                         float* __restrict__ out) {
    int w = (blockIdx.x * blockDim.x + threadIdx.x) >> 5;
    int lane = threadIdx.x & 31;
    if (w >= NS) return;
    const float4* ur = (const float4*)(u + (size_t)rows[w] * 256);
    const float4* gr = (const float4*)(g + (size_t)cols[w] * 256);
    float acc = 0.f;
#pragma unroll
    for (int i = 0; i < 2; i++) {
        float4 a = ur[lane + i * 32];
        float4 b = gr[lane + i * 32];
        acc += a.x * b.x + a.y * b.y + a.z * b.z + a.w * b.w;
    }
#pragma unroll
    for (int o = 16; o; o >>= 1) acc += __shfl_down_sync(0xffffffffu, acc, o);
    if (lane == 0) out[w] = acc;
}

// ----------------------------------------------------------------------------
// Host side
// ----------------------------------------------------------------------------
static void run_layer(const float* u_prev, int du, const float* g_prev, int dg,
                      const float* b_ug, const float* b_gu,
                      float* g_out, float* u_out, int relu, int lslot,
                      float* p_msg_g, float* p_y, float* p_msg_u,
                      int* p_rp_ug, int* p_es_ug, float* p_ws_ug,
                      int* p_rp_gu, int* p_es_gu, float* p_ws_gu,
                      __nv_bfloat16* const* wh, __nv_bfloat16* const* wl) {
    const __nv_bfloat16 *h0 = wh[lslot + 0], *l0 = wl[lslot + 0];
    const __nv_bfloat16 *h1 = wh[lslot + 1], *l1 = wl[lslot + 1];
    const __nv_bfloat16 *h2 = wh[lslot + 2], *l2 = wl[lslot + 2];
    const __nv_bfloat16 *h3 = wh[lslot + 3], *l3 = wl[lslot + 3];

    // users -> games: msg_g[NG,du] = segsum_ug(u_prev)
    if (du == 128)
        k_segsum128<<<(NG + 7) / 8, 256>>>(u_prev, p_rp_ug, p_es_ug, p_ws_ug, p_msg_g, NG);
    else
        k_segsum256<<<(NG + 7) / 8, 256>>>(u_prev, p_rp_ug, p_es_ug, p_ws_ug, p_msg_g, NG);
    // g_out = relu?(msg_g@Wr_ug + g_prev@Wo_g + b_ug)
    k_tgemm<<<dim3((NG + 127) / 128, 2), 256>>>(p_msg_g, h0, l0, du,
                                                g_prev, h1, l1, dg,
                                                nullptr, b_ug, g_out, NG, relu);
    // games -> users (commuted): y = g_prev@Wr_gu
    k_tgemm<<<dim3((NG + 127) / 128, 2), 256>>>(g_prev, h2, l2, dg,
                                                nullptr, nullptr, nullptr, 0,
                                                nullptr, nullptr, p_y, NG, 0);
    // msg_u[NU,256] = segsum_gu(y)
    k_segsum256<<<(NU + 7) / 8, 256>>>(p_y, p_rp_gu, p_es_gu, p_ws_gu, p_msg_u, NU);
    // u_out = relu?(msg_u + u_prev@Wo_u + b_gu)
    k_tgemm<<<dim3((NU + 127) / 128, 2), 256>>>(u_prev, h3, l3, du,
                                                nullptr, nullptr, nullptr, 0,
                                                p_msg_u, b_gu, u_out, NU, relu);
}

extern "C" void kernel_launch(void* const* d_in, const int* in_sizes, int n_in,
                              void* d_out, int out_size) {
    // ---- input mapping (handles both metadata orderings) ----
    const float *x_user, *x_game, *emb_game, *ew_ug, *ew_gu;
    const int *src_ug, *dst_ug, *src_gu, *dst_gu, *srow, *scol;
    const float *Wrug[3], *bug[3], *Wog[3], *Wrgu[3], *bgu[3], *Wou[3];

    x_user   = (const float*)d_in[0];
    x_game   = (const float*)d_in[1];
    emb_game = (const float*)d_in[2];
    ew_ug    = (const float*)d_in[3];
    ew_gu    = (const float*)d_in[4];

    if (in_sizes[5] == NE) {
        src_ug = (const int*)d_in[5];
        dst_ug = (const int*)d_in[6];
        src_gu = (const int*)d_in[7];
        dst_gu = (const int*)d_in[8];
        srow   = (const int*)d_in[9];
        scol   = (const int*)d_in[10];
        for (int l = 0; l < 3; l++) {
            int b = 11 + 6 * l;
            Wrug[l] = (const float*)d_in[b + 0];
            bug[l]  = (const float*)d_in[b + 1];
            Wog[l]  = (const float*)d_in[b + 2];
            Wrgu[l] = (const float*)d_in[b + 3];
            bgu[l]  = (const float*)d_in[b + 4];
            Wou[l]  = (const float*)d_in[b + 5];
        }
    } else {
        for (int l = 0; l < 3; l++) {
            int b = 5 + 6 * l;
            Wrug[l] = (const float*)d_in[b + 0];
            bug[l]  = (const float*)d_in[b + 1];
            Wog[l]  = (const float*)d_in[b + 2];
            Wrgu[l] = (const float*)d_in[b + 3];
            bgu[l]  = (const float*)d_in[b + 4];
            Wou[l]  = (const float*)d_in[b + 5];
        }
        src_ug = (const int*)d_in[23];
        dst_ug = (const int*)d_in[24];
        src_gu = (const int*)d_in[25];
        dst_gu = (const int*)d_in[26];
        srow   = (const int*)d_in[27];
        scol   = (const int*)d_in[28];
    }

    // ---- scratch symbol addresses ----
    float *p_xg, *p_u0, *p_u1, *p_g0, *p_g1, *p_msg_g, *p_y, *p_msg_u;
    float *p_ws_ug, *p_ws_gu;
    int *p_rp_ug, *p_rp_gu, *p_es_ug, *p_es_gu;
    cudaGetSymbolAddress((void**)&p_xg, d_xg);
    cudaGetSymbolAddress((void**)&p_u0, d_u0);
    cudaGetSymbolAddress((void**)&p_u1, d_u1);
    cudaGetSymbolAddress((void**)&p_g0, d_g0);
    cudaGetSymbolAddress((void**)&p_g1, d_g1);
    cudaGetSymbolAddress((void**)&p_msg_g, d_msg_g);
    cudaGetSymbolAddress((void**)&p_y, d_y);
    cudaGetSymbolAddress((void**)&p_msg_u, d_msg_u);
    cudaGetSymbolAddress((void**)&p_rp_ug, d_rp_ug);
    cudaGetSymbolAddress((void**)&p_rp_gu, d_rp_gu);
    cudaGetSymbolAddress((void**)&p_es_ug, d_es_ug);
    cudaGetSymbolAddress((void**)&p_es_gu, d_es_gu);
    cudaGetSymbolAddress((void**)&p_ws_ug, d_ws_ug);
    cudaGetSymbolAddress((void**)&p_ws_gu, d_ws_gu);

    __nv_bfloat16* wh[12];
    __nv_bfloat16* wl[12];
    {
        __nv_bfloat16* base_h;
        __nv_bfloat16* base_l;
        cudaGetSymbolAddress((void**)&base_h, d_wh);
        cudaGetSymbolAddress((void**)&base_l, d_wl);
        for (int s = 0; s < 12; s++) {
            wh[s] = base_h + (size_t)s * 256 * 256;
            wl[s] = base_l + (size_t)s * 256 * 256;
        }
    }

    float* out = (float*)d_out;

    // ---- setup: weight splits (all 12 up-front), concat, CSR build ----
    WSplitArgs wargs;
    for (int l = 0; l < 3; l++) {
        int du = (l == 0) ? 128 : 256;
        int dg = (l == 0) ? 128 : 256;
        wargs.W[4 * l + 0] = Wrug[l]; wargs.K[4 * l + 0] = du;
        wargs.W[4 * l + 1] = Wog[l];  wargs.K[4 * l + 1] = dg;
        wargs.W[4 * l + 2] = Wrgu[l]; wargs.K[4 * l + 2] = dg;
        wargs.W[4 * l + 3] = Wou[l];  wargs.K[4 * l + 3] = du;
    }
    k_wsplit_all<<<dim3(256, 12), 256>>>(wargs);

    k_concat<<<(NG * 64 + 255) / 256, 256>>>(x_game, emb_game);
    k_zero_counts<<<(NU + 256) / 256, 256>>>();
    k_hist<<<(NE + 255) / 256, 256>>>(dst_ug, dst_gu);
    k_blocksum<<<dim3(98, 2), 256>>>();
    k_scanbsum<<<1, 32>>>();
    k_scanwrite<<<dim3(98, 2), 256>>>();
    k_cursor<<<(NU + 256) / 256, 256>>>();
    k_scatter<<<(NE + 255) / 256, 256>>>(src_ug, dst_ug, ew_ug,
                                         src_gu, dst_gu, ew_gu);

    // ---- 3 GraphConv layers ----
    run_layer(x_user, 128, p_xg, 128, bug[0], bgu[0],
              p_g0, p_u0, 1, 0,
              p_msg_g, p_y, p_msg_u,
              p_rp_ug, p_es_ug, p_ws_ug, p_rp_gu, p_es_gu, p_ws_gu, wh, wl);
    run_layer(p_u0, 256, p_g0, 256, bug[1], bgu[1],
              p_g1, p_u1, 1, 4,
              p_msg_g, p_y, p_msg_u,
              p_rp_ug, p_es_ug, p_ws_ug, p_rp_gu, p_es_gu, p_ws_gu, wh, wl);
    run_layer(p_u1, 256, p_g1, 256, bug[2], bgu[2],
              p_g0, p_u0, 0, 8,
              p_msg_g, p_y, p_msg_u,
              p_rp_ug, p_es_ug, p_ws_ug, p_rp_gu, p_es_gu, p_ws_gu, wh, wl);

    // ---- decoder ----
    k_decode<<<(NS * 32 + 255) / 256, 256>>>(p_u0, p_g0, srow, scol, out);
    (void)n_in; (void)out_size;
}